// round 1
// baseline (speedup 1.0000x reference)
#include <cuda_runtime.h>

#define B_ 2
#define T_ 2048
#define C_ 1024
#define H_ 16
#define D_ 64
#define M_ (B_*T_)      // 4096 rows
#define N3_ (3*C_)      // 3072 output features
#define PAD_ 65

// Scratch: Q/K/V in [B,H,T,D] layout (16 MB each). __device__ globals per alloc rules.
__device__ float g_q[B_*H_*T_*D_];
__device__ float g_k[B_*H_*T_*D_];
__device__ float g_v[B_*H_*T_*D_];

// ---------------------------------------------------------------------------
// Kernel 1: qkv = x @ W^T + b, scattered directly into [B,H,T,D] Q/K/V layout.
// M=4096, N=3072, K=1024. 64x64 tile, BK=16, 16x16 threads, 4x4 microtile.
// ---------------------------------------------------------------------------
__global__ __launch_bounds__(256) void qkv_gemm_kernel(
    const float* __restrict__ x, const float* __restrict__ W,
    const float* __restrict__ bias)
{
    __shared__ float Xs[64][17];   // [m][kk]
    __shared__ float Ws[64][17];   // [n][kk]

    const int tx = threadIdx.x, ty = threadIdx.y;
    const int tid = ty * 16 + tx;
    const int m0 = blockIdx.y * 64;
    const int n0 = blockIdx.x * 64;
    const int lrow = tid >> 2;     // 0..63
    const int lseg = tid & 3;      // 0..3

    float acc[4][4] = {};

    const float* xp = x + (size_t)(m0 + lrow) * C_ + lseg * 4;
    const float* wp = W + (size_t)(n0 + lrow) * C_ + lseg * 4;

    for (int k0 = 0; k0 < C_; k0 += 16) {
        float4 xv = *(const float4*)(xp + k0);
        float4 wv = *(const float4*)(wp + k0);
        Xs[lrow][lseg*4+0] = xv.x;
        Xs[lrow][lseg*4+1] = xv.y;
        Xs[lrow][lseg*4+2] = xv.z;
        Xs[lrow][lseg*4+3] = xv.w;
        Ws[lrow][lseg*4+0] = wv.x;
        Ws[lrow][lseg*4+1] = wv.y;
        Ws[lrow][lseg*4+2] = wv.z;
        Ws[lrow][lseg*4+3] = wv.w;
        __syncthreads();

        #pragma unroll
        for (int kk = 0; kk < 16; kk++) {
            float rx[4], rw[4];
            #pragma unroll
            for (int i = 0; i < 4; i++) rx[i] = Xs[ty*4+i][kk];
            #pragma unroll
            for (int j = 0; j < 4; j++) rw[j] = Ws[tx*4+j][kk];
            #pragma unroll
            for (int i = 0; i < 4; i++)
                #pragma unroll
                for (int j = 0; j < 4; j++)
                    acc[i][j] += rx[i] * rw[j];
        }
        __syncthreads();
    }

    // n0 is a multiple of 64, so the whole 64-wide tile lies in one (part, head):
    const int part = n0 / C_;          // 0=q, 1=k, 2=v
    const int rem  = n0 % C_;
    const int h    = rem / D_;         // constant over the tile; d = local col
    float* dst = (part == 0) ? g_q : (part == 1 ? g_k : g_v);

    #pragma unroll
    for (int i = 0; i < 4; i++) {
        int m = m0 + ty*4 + i;
        int b = m / T_;
        int t = m - b * T_;
        float* drow = dst + ((size_t)(b * H_ + h) * T_ + t) * D_;
        #pragma unroll
        for (int j = 0; j < 4; j++) {
            int d = tx*4 + j;
            drow[d] = acc[i][j] + bias[n0 + d];
        }
    }
}

// ---------------------------------------------------------------------------
// Kernel 2: per (b, h, 64-query tile): Y = relu(Q K^T * scale, causal) @ V
// No softmax -> no running max/sum; plain GEMM-relu-GEMM with tile skipping.
// smem: Qs[64][65], KSt[64][65] (K tile, then reused as S tile), Vs[64][65].
// ---------------------------------------------------------------------------
__global__ __launch_bounds__(256) void attn_kernel(float* __restrict__ out)
{
    extern __shared__ float sm[];
    float* Qs  = sm;                  // [qi][d]
    float* KSt = sm + 64 * PAD_;      // [kj][d] -> later [qi][kj]
    float* Vs  = sm + 2 * 64 * PAD_;  // [kj][d]

    const int tx = threadIdx.x, ty = threadIdx.y;
    const int tid = ty * 16 + tx;
    const int qt = blockIdx.x, h = blockIdx.y, b = blockIdx.z;
    const int q0 = qt * 64;
    const float scale = 0.125f;       // 1/sqrt(64)

    const size_t base = (size_t)(b * H_ + h) * T_ * D_;
    const float* Qg = g_q + base;
    const float* Kg = g_k + base;
    const float* Vg = g_v + base;

    const int lrow = tid >> 2;        // 0..63
    const int lseg = tid & 3;         // 0..3 (16 floats each)

    // Load Q tile once
    #pragma unroll
    for (int u = 0; u < 4; u++) {
        float4 v = *(const float4*)(Qg + (size_t)(q0 + lrow) * D_ + lseg*16 + u*4);
        float* qp = &Qs[lrow * PAD_ + lseg*16 + u*4];
        qp[0] = v.x; qp[1] = v.y; qp[2] = v.z; qp[3] = v.w;
    }

    float accy[4][4] = {};

    for (int jt = 0; jt <= qt; jt++) {
        const int j0 = jt * 64;
        __syncthreads();   // prior-iter reads of KSt/Vs done; also fences Qs stores (iter 0)

        #pragma unroll
        for (int u = 0; u < 4; u++) {
            float4 kv = *(const float4*)(Kg + (size_t)(j0 + lrow) * D_ + lseg*16 + u*4);
            float4 vv = *(const float4*)(Vg + (size_t)(j0 + lrow) * D_ + lseg*16 + u*4);
            float* kp = &KSt[lrow * PAD_ + lseg*16 + u*4];
            kp[0] = kv.x; kp[1] = kv.y; kp[2] = kv.z; kp[3] = kv.w;
            float* vp = &Vs[lrow * PAD_ + lseg*16 + u*4];
            vp[0] = vv.x; vp[1] = vv.y; vp[2] = vv.z; vp[3] = vv.w;
        }
        __syncthreads();

        // S = Q @ K^T  (inner dim d)
        float s[4][4] = {};
        #pragma unroll 8
        for (int d = 0; d < 64; d++) {
            float rq[4], rk[4];
            #pragma unroll
            for (int i = 0; i < 4; i++) rq[i] = Qs[(ty*4+i)*PAD_ + d];
            #pragma unroll
            for (int j = 0; j < 4; j++) rk[j] = KSt[(tx*4+j)*PAD_ + d];
            #pragma unroll
            for (int i = 0; i < 4; i++)
                #pragma unroll
                for (int j = 0; j < 4; j++)
                    s[i][j] += rq[i] * rk[j];
        }

        __syncthreads();   // all K-tile reads done before overwriting with S

        // scale + ReLU + causal mask, write S tile into KSt as [qi][kj]
        #pragma unroll
        for (int i = 0; i < 4; i++) {
            int qi = q0 + ty*4 + i;
            #pragma unroll
            for (int j = 0; j < 4; j++) {
                int kj = j0 + tx*4 + j;
                float v = s[i][j] * scale;
                v = (v > 0.0f && kj <= qi) ? v : 0.0f;
                KSt[(ty*4+i)*PAD_ + (tx*4+j)] = v;
            }
        }
        __syncthreads();

        // Y += S @ V  (inner dim kk = key index)
        #pragma unroll 8
        for (int kk = 0; kk < 64; kk++) {
            float rs[4], rv[4];
            #pragma unroll
            for (int i = 0; i < 4; i++) rs[i] = KSt[(ty*4+i)*PAD_ + kk];
            #pragma unroll
            for (int j = 0; j < 4; j++) rv[j] = Vs[kk*PAD_ + tx*4+j];
            #pragma unroll
            for (int i = 0; i < 4; i++)
                #pragma unroll
                for (int j = 0; j < 4; j++)
                    accy[i][j] += rs[i] * rv[j];
        }
    }

    // out[b][t][h*D + d]  ([B,T,C] row-major)
    #pragma unroll
    for (int i = 0; i < 4; i++) {
        int t = q0 + ty*4 + i;
        float* orow = out + ((size_t)b * T_ + t) * C_ + h * D_;
        #pragma unroll
        for (int j = 0; j < 4; j++)
            orow[tx*4+j] = accy[i][j];
    }
}

extern "C" void kernel_launch(void* const* d_in, const int* in_sizes, int n_in,
                              void* d_out, int out_size)
{
    const float* x    = (const float*)d_in[0];
    const float* W    = (const float*)d_in[1];
    const float* bias = (const float*)d_in[2];
    float* out = (float*)d_out;

    const int smem_bytes = 3 * 64 * PAD_ * (int)sizeof(float);  // 49920 > 48K -> opt in
    cudaFuncSetAttribute(attn_kernel, cudaFuncAttributeMaxDynamicSharedMemorySize, smem_bytes);

    dim3 blk(16, 16);
    dim3 g1(N3_/64, M_/64);      // (48, 64)
    qkv_gemm_kernel<<<g1, blk>>>(x, W, bias);

    dim3 g2(T_/64, H_, B_);      // (32, 16, 2)
    attn_kernel<<<g2, blk, smem_bytes>>>(out);
}

// round 3
// speedup vs baseline: 4.0778x; 4.0778x over previous
#include <cuda_runtime.h>
#include <cstdint>

#define B_ 2
#define T_ 2048
#define C_ 1024
#define H_ 16
#define D_ 64

// Scratch: Q,K in [b,h,t,d]; V transposed in [b,h,d,t].
__device__ float g_q [B_*H_*T_*D_];
__device__ float g_k [B_*H_*T_*D_];
__device__ float g_vt[B_*H_*D_*T_];

// ---------------------------------------------------------------------------
// helpers (all base sm_80 PTX — legal on compute_103 family target)
// ---------------------------------------------------------------------------
__device__ __forceinline__ uint32_t smem_u32(const void* p){
    uint32_t a;
    asm("{ .reg .u64 t; cvta.to.shared.u64 t, %1; cvt.u32.u64 %0, t; }" : "=r"(a) : "l"(p));
    return a;
}
__device__ __forceinline__ uint32_t f2tf(float f){
    uint32_t r; asm("cvt.rna.tf32.f32 %0, %1;" : "=r"(r) : "f"(f)); return r;
}
__device__ __forceinline__ void sts128(uint32_t a, uint32_t x, uint32_t y, uint32_t z, uint32_t w){
    asm volatile("st.shared.v4.b32 [%0], {%1,%2,%3,%4};" :: "r"(a), "r"(x), "r"(y), "r"(z), "r"(w) : "memory");
}
__device__ __forceinline__ void sts64f(uint32_t a, float x, float y){
    asm volatile("st.shared.v2.f32 [%0], {%1,%2};" :: "r"(a), "f"(x), "f"(y) : "memory");
}
__device__ __forceinline__ void ldsm4(uint32_t (&r)[4], uint32_t a){
    asm volatile("ldmatrix.sync.aligned.m8n8.x4.shared.b16 {%0,%1,%2,%3}, [%4];"
        : "=r"(r[0]), "=r"(r[1]), "=r"(r[2]), "=r"(r[3]) : "r"(a));
}
__device__ __forceinline__ void mma8(float (&d)[4], const uint32_t (&a)[4], uint32_t b0, uint32_t b1){
    asm volatile("mma.sync.aligned.m16n8k8.row.col.f32.tf32.tf32.f32 "
        "{%0,%1,%2,%3}, {%4,%5,%6,%7}, {%8,%9}, {%0,%1,%2,%3};"
        : "+f"(d[0]), "+f"(d[1]), "+f"(d[2]), "+f"(d[3])
        : "r"(a[0]), "r"(a[1]), "r"(a[2]), "r"(a[3]), "r"(b0), "r"(b1));
}

// ---------------------------------------------------------------------------
// Kernel 1: QKV = x @ W^T + b   (M=4096, N=3072, K=1024), tf32 mma.sync.
// 128x128 CTA tile, BK=32, 8 warps (2m x 4n), warp tile 64x32, double buffer.
// ---------------------------------------------------------------------------
__global__ __launch_bounds__(256) void qkv_mma_kernel(
    const float* __restrict__ x, const float* __restrict__ W,
    const float* __restrict__ bias)
{
    extern __shared__ __align__(1024) char smem[];
    const uint32_t s0 = smem_u32(smem);           // A0@0 B0@16K A1@32K B1@48K
    const int tid = threadIdx.x, lane = tid & 31, wid = tid >> 5;
    const int wm = wid >> 2, wn = wid & 3;
    const int m0 = blockIdx.y * 128, n0 = blockIdx.x * 128;

    const int rx   = lane & 7;
    const int arow = (lane & 7) + ((lane >> 3) & 1) * 8;  // + mi*16 + wm*64
    const int ahi  = lane >> 4;
    const int brow = (lane & 7) + ((lane >> 4) << 3);     // + pr*16 + wn*32
    const int bhi  = (lane >> 3) & 1;

    float acc[4][4][4] = {};
    float4 ra[4], rb[4];
    int lrow[4], lchk[4];
    #pragma unroll
    for (int i = 0; i < 4; i++) { int s = tid + 256 * i; lrow[i] = s >> 3; lchk[i] = s & 7; }

    auto LDG = [&](int kt) {
        #pragma unroll
        for (int i = 0; i < 4; i++) {
            ra[i] = __ldg((const float4*)(x + (size_t)(m0 + lrow[i]) * C_ + kt * 32 + lchk[i] * 4));
            rb[i] = __ldg((const float4*)(W + (size_t)(n0 + lrow[i]) * C_ + kt * 32 + lchk[i] * 4));
        }
    };
    auto STS = [&](uint32_t Ab, uint32_t Bb) {
        #pragma unroll
        for (int i = 0; i < 4; i++) {
            uint32_t off = lrow[i] * 128 + ((lchk[i] ^ (lrow[i] & 7)) << 4);
            sts128(Ab + off, f2tf(ra[i].x), f2tf(ra[i].y), f2tf(ra[i].z), f2tf(ra[i].w));
            sts128(Bb + off, f2tf(rb[i].x), f2tf(rb[i].y), f2tf(rb[i].z), f2tf(rb[i].w));
        }
    };

    LDG(0); STS(s0, s0 + 16384);
    __syncthreads();

    for (int kt = 0; kt < 32; kt++) {
        const int p = kt & 1;
        if (kt < 31) LDG(kt + 1);
        const uint32_t Ab = s0 + p * 32768, Bb = Ab + 16384;
        #pragma unroll
        for (int ks = 0; ks < 4; ks++) {
            uint32_t a[4][4], b[2][4];
            #pragma unroll
            for (int mi = 0; mi < 4; mi++)
                ldsm4(a[mi], Ab + (wm*64 + mi*16 + arow) * 128 + (((ks*2 + ahi) ^ rx) << 4));
            #pragma unroll
            for (int pr = 0; pr < 2; pr++)
                ldsm4(b[pr], Bb + (wn*32 + pr*16 + brow) * 128 + (((ks*2 + bhi) ^ rx) << 4));
            #pragma unroll
            for (int mi = 0; mi < 4; mi++)
                #pragma unroll
                for (int ni = 0; ni < 4; ni++)
                    mma8(acc[mi][ni], a[mi], b[ni>>1][(ni&1)*2], b[ni>>1][(ni&1)*2+1]);
        }
        if (kt < 31) STS(s0 + (1-p) * 32768, s0 + (1-p) * 32768 + 16384);
        __syncthreads();
    }

    // Epilogue: scatter Q,K -> [b,h,t,d]; V -> [b,h,d,t]; add bias.
    #pragma unroll
    for (int mi = 0; mi < 4; mi++) {
        #pragma unroll
        for (int half = 0; half < 2; half++) {
            const int m = m0 + wm*64 + mi*16 + (lane >> 2) + half*8;
            const int bb = m >> 11, t = m & 2047;
            #pragma unroll
            for (int ni = 0; ni < 4; ni++) {
                const int n = n0 + wn*32 + ni*8 + 2*(lane & 3);
                const int part = n >> 10, hh = (n >> 6) & 15, d = n & 63;
                const float v0 = acc[mi][ni][half*2+0] + __ldg(bias + n);
                const float v1 = acc[mi][ni][half*2+1] + __ldg(bias + n + 1);
                if (part < 2) {
                    float* dst = (part == 0 ? g_q : g_k) + (((size_t)(bb*H_ + hh) * T_ + t) * D_ + d);
                    *(float2*)dst = make_float2(v0, v1);
                } else {
                    float* dst = g_vt + (((size_t)(bb*H_ + hh) * D_ + d) * T_ + t);
                    dst[0] = v0; dst[T_] = v1;
                }
            }
        }
    }
}

// ---------------------------------------------------------------------------
// Kernel 2: per (b,h,128-query tile): Y = relu(Q K^T * scale, causal) @ V
// MMA1 (M128 N128 K64) -> regs -> relu/mask -> tf32 smem S -> MMA2 (M128 N64 K128).
// Y accumulated in registers across causal key tiles.
// ---------------------------------------------------------------------------
__global__ __launch_bounds__(256) void attn_mma_kernel(float* __restrict__ out)
{
    extern __shared__ __align__(1024) char smem[];
    const uint32_t s0 = smem_u32(smem);
    const uint32_t Qs = s0, Ks = s0 + 32768, Vs = s0 + 65536, Ss = s0 + 98304;
    const int tid = threadIdx.x, lane = tid & 31, wid = tid >> 5;
    const int wm = wid >> 2, wn = wid & 3;
    const int qt = blockIdx.x, h = blockIdx.y, bb = blockIdx.z;
    const int q0 = qt * 128;
    const size_t bh = (size_t)(bb * H_ + h);
    const float* Qg  = g_q  + bh * T_ * D_;
    const float* Kg  = g_k  + bh * T_ * D_;
    const float* Vtg = g_vt + bh * (size_t)D_ * T_;

    const int rx   = lane & 7;
    const int arow = (lane & 7) + ((lane >> 3) & 1) * 8;
    const int ahi  = lane >> 4;
    const int brow = (lane & 7) + ((lane >> 4) << 3);
    const int bhi  = (lane >> 3) & 1;

    // Q tile: 128 x 64 (ROWB=256)
    #pragma unroll
    for (int i = 0; i < 8; i++) {
        int s = tid + 256 * i, row = s >> 4, c = s & 15;
        float4 v = __ldg((const float4*)(Qg + (size_t)(q0 + row) * D_ + c * 4));
        sts128(Qs + row * 256 + ((c ^ (row & 7)) << 4), f2tf(v.x), f2tf(v.y), f2tf(v.z), f2tf(v.w));
    }

    float accY[4][2][4] = {};

    for (int jt = 0; jt <= qt; jt++) {
        const int j0 = jt * 128;
        __syncthreads();    // prev iter's MMA2 done reading S,V (and Q stores fenced via next sync)

        // K tile: 128 x 64 (ROWB=256)
        #pragma unroll
        for (int i = 0; i < 8; i++) {
            int s = tid + 256 * i, row = s >> 4, c = s & 15;
            float4 v = __ldg((const float4*)(Kg + (size_t)(j0 + row) * D_ + c * 4));
            sts128(Ks + row * 256 + ((c ^ (row & 7)) << 4), f2tf(v.x), f2tf(v.y), f2tf(v.z), f2tf(v.w));
        }
        // V tile: Vt 64 x 128 (ROWB=512)
        #pragma unroll
        for (int i = 0; i < 8; i++) {
            int s = tid + 256 * i, row = s >> 5, c = s & 31;
            float4 v = __ldg((const float4*)(Vtg + (size_t)row * T_ + j0 + c * 4));
            sts128(Vs + row * 512 + ((c ^ (row & 7)) << 4), f2tf(v.x), f2tf(v.y), f2tf(v.z), f2tf(v.w));
        }
        __syncthreads();

        // MMA1: S = Q @ K^T  (K=64 -> 8 k-steps)
        float accS[4][4][4] = {};
        #pragma unroll
        for (int ks = 0; ks < 8; ks++) {
            uint32_t a[4][4], b[2][4];
            #pragma unroll
            for (int mi = 0; mi < 4; mi++)
                ldsm4(a[mi], Qs + (wm*64 + mi*16 + arow) * 256 + (((ks*2 + ahi) ^ rx) << 4));
            #pragma unroll
            for (int pr = 0; pr < 2; pr++)
                ldsm4(b[pr], Ks + (wn*32 + pr*16 + brow) * 256 + (((ks*2 + bhi) ^ rx) << 4));
            #pragma unroll
            for (int mi = 0; mi < 4; mi++)
                #pragma unroll
                for (int ni = 0; ni < 4; ni++)
                    mma8(accS[mi][ni], a[mi], b[ni>>1][(ni&1)*2], b[ni>>1][(ni&1)*2+1]);
        }

        // scale + causal ReLU -> tf32 -> S smem ([q][kj], ROWB=512)
        #pragma unroll
        for (int mi = 0; mi < 4; mi++) {
            #pragma unroll
            for (int half = 0; half < 2; half++) {
                const int r  = wm*64 + mi*16 + (lane >> 2) + half*8;
                const int qi = q0 + r;
                #pragma unroll
                for (int ni = 0; ni < 4; ni++) {
                    const int c  = wn*32 + ni*8 + 2*(lane & 3);
                    const int kj = j0 + c;
                    float v0 = accS[mi][ni][half*2+0] * 0.125f;
                    float v1 = accS[mi][ni][half*2+1] * 0.125f;
                    v0 = (v0 > 0.f && kj     <= qi) ? v0 : 0.f;
                    v1 = (v1 > 0.f && kj + 1 <= qi) ? v1 : 0.f;
                    uint32_t addr = Ss + r * 512 + (((c >> 2) ^ (r & 7)) << 4) + (c & 3) * 4;
                    sts64f(addr, __uint_as_float(f2tf(v0)), __uint_as_float(f2tf(v1)));
                }
            }
        }
        __syncthreads();

        // MMA2: Y += S @ Vt^T  (K=128 -> 16 k-steps, N=64: warp covers 16 cols)
        #pragma unroll
        for (int ks = 0; ks < 16; ks++) {
            uint32_t a[4][4], b[4];
            #pragma unroll
            for (int mi = 0; mi < 4; mi++)
                ldsm4(a[mi], Ss + (wm*64 + mi*16 + arow) * 512 + (((ks*2 + ahi) ^ rx) << 4));
            ldsm4(b, Vs + (wn*16 + brow) * 512 + (((ks*2 + bhi) ^ rx) << 4));
            #pragma unroll
            for (int mi = 0; mi < 4; mi++) {
                mma8(accY[mi][0], a[mi], b[0], b[1]);
                mma8(accY[mi][1], a[mi], b[2], b[3]);
            }
        }
    }

    // Y epilogue -> out[b, t, h*64 + d]
    #pragma unroll
    for (int mi = 0; mi < 4; mi++) {
        #pragma unroll
        for (int half = 0; half < 2; half++) {
            const int t = q0 + wm*64 + mi*16 + (lane >> 2) + half*8;
            float* orow = out + ((size_t)bb * T_ + t) * C_ + h * D_;
            #pragma unroll
            for (int ni = 0; ni < 2; ni++) {
                const int d = wn*16 + ni*8 + 2*(lane & 3);
                *(float2*)(orow + d) = make_float2(accY[mi][ni][half*2+0], accY[mi][ni][half*2+1]);
            }
        }
    }
}

extern "C" void kernel_launch(void* const* d_in, const int* in_sizes, int n_in,
                              void* d_out, int out_size)
{
    const float* x    = (const float*)d_in[0];
    const float* W    = (const float*)d_in[1];
    const float* bias = (const float*)d_in[2];
    float* out = (float*)d_out;

    const int qkv_smem  = 65536;    // 2 x (16KB A + 16KB B)
    const int attn_smem = 163840;   // Q32K + K32K + V32K + S64K
    cudaFuncSetAttribute(qkv_mma_kernel,  cudaFuncAttributeMaxDynamicSharedMemorySize, qkv_smem);
    cudaFuncSetAttribute(attn_mma_kernel, cudaFuncAttributeMaxDynamicSharedMemorySize, attn_smem);

    dim3 g1(24, 32);          // N/128 x M/128
    qkv_mma_kernel<<<g1, 256, qkv_smem>>>(x, W, bias);

    dim3 g2(16, 16, 2);       // q-tiles x heads x batch
    attn_mma_kernel<<<g2, 256, attn_smem>>>(out);
}

// round 4
// speedup vs baseline: 4.1205x; 1.0105x over previous
#include <cuda_runtime.h>
#include <cstdint>

#define B_ 2
#define T_ 2048
#define C_ 1024
#define H_ 16
#define D_ 64

// Scratch (tf32-rounded values): Q,K in [b,h,t,d]; V transposed in [b,h,d,t].
__device__ float g_q [B_*H_*T_*D_];
__device__ float g_k [B_*H_*T_*D_];
__device__ float g_vt[B_*H_*D_*T_];

// ---------------------------------------------------------------------------
// helpers (all base sm_80 PTX — legal on compute_103 family target)
// ---------------------------------------------------------------------------
__device__ __forceinline__ uint32_t smem_u32(const void* p){
    uint32_t a;
    asm("{ .reg .u64 t; cvta.to.shared.u64 t, %1; cvt.u32.u64 %0, t; }" : "=r"(a) : "l"(p));
    return a;
}
__device__ __forceinline__ uint32_t f2tf(float f){
    uint32_t r; asm("cvt.rna.tf32.f32 %0, %1;" : "=r"(r) : "f"(f)); return r;
}
__device__ __forceinline__ void sts128(uint32_t a, uint32_t x, uint32_t y, uint32_t z, uint32_t w){
    asm volatile("st.shared.v4.b32 [%0], {%1,%2,%3,%4};" :: "r"(a), "r"(x), "r"(y), "r"(z), "r"(w) : "memory");
}
__device__ __forceinline__ void sts64f(uint32_t a, float x, float y){
    asm volatile("st.shared.v2.f32 [%0], {%1,%2};" :: "r"(a), "f"(x), "f"(y) : "memory");
}
__device__ __forceinline__ void ldsm4(uint32_t (&r)[4], uint32_t a){
    asm volatile("ldmatrix.sync.aligned.m8n8.x4.shared.b16 {%0,%1,%2,%3}, [%4];"
        : "=r"(r[0]), "=r"(r[1]), "=r"(r[2]), "=r"(r[3]) : "r"(a));
}
__device__ __forceinline__ void mma8(float (&d)[4], const uint32_t (&a)[4], uint32_t b0, uint32_t b1){
    asm volatile("mma.sync.aligned.m16n8k8.row.col.f32.tf32.tf32.f32 "
        "{%0,%1,%2,%3}, {%4,%5,%6,%7}, {%8,%9}, {%0,%1,%2,%3};"
        : "+f"(d[0]), "+f"(d[1]), "+f"(d[2]), "+f"(d[3])
        : "r"(a[0]), "r"(a[1]), "r"(a[2]), "r"(a[3]), "r"(b0), "r"(b1));
}
__device__ __forceinline__ void cp16(uint32_t dst, const void* src){
    asm volatile("cp.async.ca.shared.global [%0], [%1], 16;" :: "r"(dst), "l"(src) : "memory");
}
__device__ __forceinline__ void cp_commit(){ asm volatile("cp.async.commit_group;" ::: "memory"); }
__device__ __forceinline__ void cp_wait0(){ asm volatile("cp.async.wait_group 0;" ::: "memory"); }

// ---------------------------------------------------------------------------
// Kernel 1: QKV = x @ W^T + b   (M=4096, N=3072, K=1024), tf32 mma.sync.
// 128x128 CTA tile, BK=32, 8 warps (2m x 4n), warp tile 64x32, double buffer.
// Outputs are tf32-rounded. V goes out transposed via a smem transpose.
// ---------------------------------------------------------------------------
__global__ __launch_bounds__(256) void qkv_mma_kernel(
    const float* __restrict__ x, const float* __restrict__ W,
    const float* __restrict__ bias)
{
    extern __shared__ __align__(1024) char smem[];
    const uint32_t s0 = smem_u32(smem);           // A0@0 B0@16K A1@32K B1@48K
    const int tid = threadIdx.x, lane = tid & 31, wid = tid >> 5;
    const int wm = wid >> 2, wn = wid & 3;
    const int m0 = blockIdx.y * 128, n0 = blockIdx.x * 128;

    const int rx   = lane & 7;
    const int arow = (lane & 7) + ((lane >> 3) & 1) * 8;
    const int ahi  = lane >> 4;
    const int brow = (lane & 7) + ((lane >> 4) << 3);
    const int bhi  = (lane >> 3) & 1;

    float acc[4][4][4] = {};
    float4 ra[4], rb[4];
    int lrow[4], lchk[4];
    #pragma unroll
    for (int i = 0; i < 4; i++) { int s = tid + 256 * i; lrow[i] = s >> 3; lchk[i] = s & 7; }

    auto LDG = [&](int kt) {
        #pragma unroll
        for (int i = 0; i < 4; i++) {
            ra[i] = __ldg((const float4*)(x + (size_t)(m0 + lrow[i]) * C_ + kt * 32 + lchk[i] * 4));
            rb[i] = __ldg((const float4*)(W + (size_t)(n0 + lrow[i]) * C_ + kt * 32 + lchk[i] * 4));
        }
    };
    auto STS = [&](uint32_t Ab, uint32_t Bb) {
        #pragma unroll
        for (int i = 0; i < 4; i++) {
            uint32_t off = lrow[i] * 128 + ((lchk[i] ^ (lrow[i] & 7)) << 4);
            sts128(Ab + off, f2tf(ra[i].x), f2tf(ra[i].y), f2tf(ra[i].z), f2tf(ra[i].w));
            sts128(Bb + off, f2tf(rb[i].x), f2tf(rb[i].y), f2tf(rb[i].z), f2tf(rb[i].w));
        }
    };

    LDG(0); STS(s0, s0 + 16384);
    __syncthreads();

    for (int kt = 0; kt < 32; kt++) {
        const int p = kt & 1;
        if (kt < 31) LDG(kt + 1);
        const uint32_t Ab = s0 + p * 32768, Bb = Ab + 16384;
        #pragma unroll
        for (int ks = 0; ks < 4; ks++) {
            uint32_t a[4][4], b[2][4];
            #pragma unroll
            for (int mi = 0; mi < 4; mi++)
                ldsm4(a[mi], Ab + (wm*64 + mi*16 + arow) * 128 + (((ks*2 + ahi) ^ rx) << 4));
            #pragma unroll
            for (int pr = 0; pr < 2; pr++)
                ldsm4(b[pr], Bb + (wn*32 + pr*16 + brow) * 128 + (((ks*2 + bhi) ^ rx) << 4));
            #pragma unroll
            for (int mi = 0; mi < 4; mi++)
                #pragma unroll
                for (int ni = 0; ni < 4; ni++)
                    mma8(acc[mi][ni], a[mi], b[ni>>1][(ni&1)*2], b[ni>>1][(ni&1)*2+1]);
        }
        if (kt < 31) STS(s0 + (1-p) * 32768, s0 + (1-p) * 32768 + 16384);
        __syncthreads();
    }

    const int part = n0 >> 10;   // whole CTA tile is in one part (128 | 1024)
    if (part < 2) {
        // Q,K -> [b,h,t,d], tf32-rounded, float2 stores.
        #pragma unroll
        for (int mi = 0; mi < 4; mi++) {
            #pragma unroll
            for (int half = 0; half < 2; half++) {
                const int m = m0 + wm*64 + mi*16 + (lane >> 2) + half*8;
                const int bb = m >> 11, t = m & 2047;
                #pragma unroll
                for (int ni = 0; ni < 4; ni++) {
                    const int n = n0 + wn*32 + ni*8 + 2*(lane & 3);
                    const int hh = (n >> 6) & 15, d = n & 63;
                    const float v0 = __uint_as_float(f2tf(acc[mi][ni][half*2+0] + __ldg(bias + n)));
                    const float v1 = __uint_as_float(f2tf(acc[mi][ni][half*2+1] + __ldg(bias + n + 1)));
                    float* dst = (part == 0 ? g_q : g_k) + (((size_t)(bb*H_ + hh) * T_ + t) * D_ + d);
                    *(float2*)dst = make_float2(v0, v1);
                }
            }
        }
    } else {
        // V -> smem transpose [n_local][m_local] (pitch 132) -> coalesced [b,h,d,t].
        float* sv = (float*)smem;
        #pragma unroll
        for (int mi = 0; mi < 4; mi++) {
            #pragma unroll
            for (int half = 0; half < 2; half++) {
                const int ml = wm*64 + mi*16 + (lane >> 2) + half*8;
                #pragma unroll
                for (int ni = 0; ni < 4; ni++) {
                    const int nl = wn*32 + ni*8 + 2*(lane & 3);
                    const int n = n0 + nl;
                    sv[(nl    ) * 132 + ml] = __uint_as_float(f2tf(acc[mi][ni][half*2+0] + __ldg(bias + n)));
                    sv[(nl + 1) * 132 + ml] = __uint_as_float(f2tf(acc[mi][ni][half*2+1] + __ldg(bias + n + 1)));
                }
            }
        }
        __syncthreads();
        const int hh = (n0 & 1023) >> 6;
        const int bb = m0 >> 11, t0 = m0 & 2047;
        #pragma unroll
        for (int i = 0; i < 16; i++) {
            const int idx = tid + 256 * i;
            const int row = idx >> 5, ch = idx & 31;
            float4 v = *(const float4*)(sv + row * 132 + ch * 4);
            const int h = hh + (row >> 6), d = row & 63;
            *(float4*)(g_vt + ((size_t)(bb*H_ + h) * D_ + d) * T_ + t0 + ch * 4) = v;
        }
    }
}

// ---------------------------------------------------------------------------
// Kernel 2: per (b,h,128-query tile): Y = relu(Q K^T * scale, causal) @ V
// cp.async double-buffered K/V (loads overlap MMA1/epilogue/MMA2), 2 syncs/iter.
// LPT: longest causal CTAs (qt=15) launch first.
// ---------------------------------------------------------------------------
__global__ __launch_bounds__(256) void attn_mma_kernel(float* __restrict__ out)
{
    extern __shared__ __align__(1024) char smem[];
    const uint32_t s0 = smem_u32(smem);
    const uint32_t Qs = s0;
    const uint32_t Kst[2] = { s0 + 32768,  s0 + 98304  };
    const uint32_t Vst[2] = { s0 + 65536,  s0 + 131072 };
    const uint32_t Ss = s0 + 163840;                       // 64KB, total 224KB

    const int tid = threadIdx.x, lane = tid & 31, wid = tid >> 5;
    const int wm = wid >> 2, wn = wid & 3;
    const int qt = (int)(gridDim.x - 1) - (int)blockIdx.x;  // LPT order
    const int h = blockIdx.y, bb = blockIdx.z;
    const int q0 = qt * 128;
    const size_t bh = (size_t)(bb * H_ + h);
    const float* Qg  = g_q  + bh * T_ * D_;
    const float* Kg  = g_k  + bh * T_ * D_;
    const float* Vtg = g_vt + bh * (size_t)D_ * T_;

    const int rx   = lane & 7;
    const int arow = (lane & 7) + ((lane >> 3) & 1) * 8;
    const int ahi  = lane >> 4;
    const int brow = (lane & 7) + ((lane >> 4) << 3);
    const int bhi  = (lane >> 3) & 1;

    auto loadKV = [&](int jt, int st) {
        const int j0 = jt * 128;
        #pragma unroll
        for (int i = 0; i < 8; i++) {           // K: 128 x 64
            int s = tid + 256 * i, row = s >> 4, c = s & 15;
            cp16(Kst[st] + row * 256 + ((c ^ (row & 7)) << 4),
                 Kg + (size_t)(j0 + row) * D_ + c * 4);
        }
        #pragma unroll
        for (int i = 0; i < 8; i++) {           // Vt: 64 x 128
            int s = tid + 256 * i, row = s >> 5, c = s & 31;
            cp16(Vst[st] + row * 512 + ((c ^ (row & 7)) << 4),
                 Vtg + (size_t)row * T_ + j0 + c * 4);
        }
    };

    // Prologue: Q + KV(0) in one cp.async group.
    #pragma unroll
    for (int i = 0; i < 8; i++) {
        int s = tid + 256 * i, row = s >> 4, c = s & 15;
        cp16(Qs + row * 256 + ((c ^ (row & 7)) << 4),
             Qg + (size_t)(q0 + row) * D_ + c * 4);
    }
    loadKV(0, 0);
    cp_commit();

    float accY[4][2][4] = {};

    for (int jt = 0; jt <= qt; jt++) {
        const int p = jt & 1;
        const int j0 = jt * 128;
        cp_wait0();
        __syncthreads();                         // buf[p] ready; prev MMA2 reads done
        if (jt < qt) { loadKV(jt + 1, 1 - p); cp_commit(); }

        // MMA1: S = Q @ K^T  (K=64 -> 8 k-steps)
        float accS[4][4][4] = {};
        #pragma unroll
        for (int ks = 0; ks < 8; ks++) {
            uint32_t a[4][4], b[2][4];
            #pragma unroll
            for (int mi = 0; mi < 4; mi++)
                ldsm4(a[mi], Qs + (wm*64 + mi*16 + arow) * 256 + (((ks*2 + ahi) ^ rx) << 4));
            #pragma unroll
            for (int pr = 0; pr < 2; pr++)
                ldsm4(b[pr], Kst[p] + (wn*32 + pr*16 + brow) * 256 + (((ks*2 + bhi) ^ rx) << 4));
            #pragma unroll
            for (int mi = 0; mi < 4; mi++)
                #pragma unroll
                for (int ni = 0; ni < 4; ni++)
                    mma8(accS[mi][ni], a[mi], b[ni>>1][(ni&1)*2], b[ni>>1][(ni&1)*2+1]);
        }

        // scale + causal ReLU -> tf32 -> S smem ([q][kj], ROWB=512)
        #pragma unroll
        for (int mi = 0; mi < 4; mi++) {
            #pragma unroll
            for (int half = 0; half < 2; half++) {
                const int r  = wm*64 + mi*16 + (lane >> 2) + half*8;
                const int qi = q0 + r;
                #pragma unroll
                for (int ni = 0; ni < 4; ni++) {
                    const int c  = wn*32 + ni*8 + 2*(lane & 3);
                    const int kj = j0 + c;
                    float v0 = accS[mi][ni][half*2+0] * 0.125f;
                    float v1 = accS[mi][ni][half*2+1] * 0.125f;
                    v0 = (v0 > 0.f && kj     <= qi) ? v0 : 0.f;
                    v1 = (v1 > 0.f && kj + 1 <= qi) ? v1 : 0.f;
                    uint32_t addr = Ss + r * 512 + (((c >> 2) ^ (r & 7)) << 4) + (c & 3) * 4;
                    sts64f(addr, __uint_as_float(f2tf(v0)), __uint_as_float(f2tf(v1)));
                }
            }
        }
        __syncthreads();

        // MMA2: Y += S @ Vt^T  (K=128 -> 16 k-steps, warp covers 16 N-cols)
        #pragma unroll
        for (int ks = 0; ks < 16; ks++) {
            uint32_t a[4][4], b[4];
            #pragma unroll
            for (int mi = 0; mi < 4; mi++)
                ldsm4(a[mi], Ss + (wm*64 + mi*16 + arow) * 512 + (((ks*2 + ahi) ^ rx) << 4));
            ldsm4(b, Vst[p] + (wn*16 + brow) * 512 + (((ks*2 + bhi) ^ rx) << 4));
            #pragma unroll
            for (int mi = 0; mi < 4; mi++) {
                mma8(accY[mi][0], a[mi], b[0], b[1]);
                mma8(accY[mi][1], a[mi], b[2], b[3]);
            }
        }
    }

    // Y epilogue -> out[b, t, h*64 + d]
    #pragma unroll
    for (int mi = 0; mi < 4; mi++) {
        #pragma unroll
        for (int half = 0; half < 2; half++) {
            const int t = q0 + wm*64 + mi*16 + (lane >> 2) + half*8;
            float* orow = out + ((size_t)bb * T_ + t) * C_ + h * D_;
            #pragma unroll
            for (int ni = 0; ni < 2; ni++) {
                const int d = wn*16 + ni*8 + 2*(lane & 3);
                *(float2*)(orow + d) = make_float2(accY[mi][ni][half*2+0], accY[mi][ni][half*2+1]);
            }
        }
    }
}

extern "C" void kernel_launch(void* const* d_in, const int* in_sizes, int n_in,
                              void* d_out, int out_size)
{
    const float* x    = (const float*)d_in[0];
    const float* W    = (const float*)d_in[1];
    const float* bias = (const float*)d_in[2];
    float* out = (float*)d_out;

    const int qkv_smem  = 67584;    // max(4x16KB tiles, 128x132 fp32 transpose)
    const int attn_smem = 229376;   // Q32K + 2x(K32K+V32K) + S64K
    cudaFuncSetAttribute(qkv_mma_kernel,  cudaFuncAttributeMaxDynamicSharedMemorySize, qkv_smem);
    cudaFuncSetAttribute(attn_mma_kernel, cudaFuncAttributeMaxDynamicSharedMemorySize, attn_smem);

    dim3 g1(24, 32);          // N/128 x M/128
    qkv_mma_kernel<<<g1, 256, qkv_smem>>>(x, W, bias);

    dim3 g2(16, 16, 2);       // q-tiles x heads x batch
    attn_mma_kernel<<<g2, 256, attn_smem>>>(out);
}

// round 5
// speedup vs baseline: 4.6853x; 1.1371x over previous
#include <cuda_runtime.h>
#include <cstdint>

#define B_ 2
#define T_ 2048
#define C_ 1024
#define H_ 16
#define D_ 64

// Scratch (tf32-rounded values): Q,K in [b,h,t,d]; V transposed in [b,h,d,t].
__device__ float g_q [B_*H_*T_*D_];
__device__ float g_k [B_*H_*T_*D_];
__device__ float g_vt[B_*H_*D_*T_];

// ---------------------------------------------------------------------------
// helpers (all base sm_80 PTX — legal on compute_103 family target)
// ---------------------------------------------------------------------------
__device__ __forceinline__ uint32_t smem_u32(const void* p){
    uint32_t a;
    asm("{ .reg .u64 t; cvta.to.shared.u64 t, %1; cvt.u32.u64 %0, t; }" : "=r"(a) : "l"(p));
    return a;
}
__device__ __forceinline__ uint32_t f2tf(float f){
    uint32_t r; asm("cvt.rna.tf32.f32 %0, %1;" : "=r"(r) : "f"(f)); return r;
}
__device__ __forceinline__ void sts128(uint32_t a, uint32_t x, uint32_t y, uint32_t z, uint32_t w){
    asm volatile("st.shared.v4.b32 [%0], {%1,%2,%3,%4};" :: "r"(a), "r"(x), "r"(y), "r"(z), "r"(w) : "memory");
}
__device__ __forceinline__ void ldsm4(uint32_t (&r)[4], uint32_t a){
    asm volatile("ldmatrix.sync.aligned.m8n8.x4.shared.b16 {%0,%1,%2,%3}, [%4];"
        : "=r"(r[0]), "=r"(r[1]), "=r"(r[2]), "=r"(r[3]) : "r"(a));
}
__device__ __forceinline__ void mma8(float (&d)[4], const uint32_t (&a)[4], uint32_t b0, uint32_t b1){
    asm volatile("mma.sync.aligned.m16n8k8.row.col.f32.tf32.tf32.f32 "
        "{%0,%1,%2,%3}, {%4,%5,%6,%7}, {%8,%9}, {%0,%1,%2,%3};"
        : "+f"(d[0]), "+f"(d[1]), "+f"(d[2]), "+f"(d[3])
        : "r"(a[0]), "r"(a[1]), "r"(a[2]), "r"(a[3]), "r"(b0), "r"(b1));
}
__device__ __forceinline__ void mma8u(float (&d)[4], uint32_t a0, uint32_t a1, uint32_t a2, uint32_t a3,
                                      uint32_t b0, uint32_t b1){
    asm volatile("mma.sync.aligned.m16n8k8.row.col.f32.tf32.tf32.f32 "
        "{%0,%1,%2,%3}, {%4,%5,%6,%7}, {%8,%9}, {%0,%1,%2,%3};"
        : "+f"(d[0]), "+f"(d[1]), "+f"(d[2]), "+f"(d[3])
        : "r"(a0), "r"(a1), "r"(a2), "r"(a3), "r"(b0), "r"(b1));
}
__device__ __forceinline__ void cp16(uint32_t dst, const void* src){
    asm volatile("cp.async.ca.shared.global [%0], [%1], 16;" :: "r"(dst), "l"(src) : "memory");
}
__device__ __forceinline__ void cp_commit(){ asm volatile("cp.async.commit_group;" ::: "memory"); }
__device__ __forceinline__ void cp_wait0(){ asm volatile("cp.async.wait_group 0;" ::: "memory"); }

// ---------------------------------------------------------------------------
// Kernel 1: QKV = x @ W^T + b   (unchanged from R4 — known good)
// ---------------------------------------------------------------------------
__global__ __launch_bounds__(256) void qkv_mma_kernel(
    const float* __restrict__ x, const float* __restrict__ W,
    const float* __restrict__ bias)
{
    extern __shared__ __align__(1024) char smem[];
    const uint32_t s0 = smem_u32(smem);
    const int tid = threadIdx.x, lane = tid & 31, wid = tid >> 5;
    const int wm = wid >> 2, wn = wid & 3;
    const int m0 = blockIdx.y * 128, n0 = blockIdx.x * 128;

    const int rx   = lane & 7;
    const int arow = (lane & 7) + ((lane >> 3) & 1) * 8;
    const int ahi  = lane >> 4;
    const int brow = (lane & 7) + ((lane >> 4) << 3);
    const int bhi  = (lane >> 3) & 1;

    float acc[4][4][4] = {};
    float4 ra[4], rb[4];
    int lrow[4], lchk[4];
    #pragma unroll
    for (int i = 0; i < 4; i++) { int s = tid + 256 * i; lrow[i] = s >> 3; lchk[i] = s & 7; }

    auto LDG = [&](int kt) {
        #pragma unroll
        for (int i = 0; i < 4; i++) {
            ra[i] = __ldg((const float4*)(x + (size_t)(m0 + lrow[i]) * C_ + kt * 32 + lchk[i] * 4));
            rb[i] = __ldg((const float4*)(W + (size_t)(n0 + lrow[i]) * C_ + kt * 32 + lchk[i] * 4));
        }
    };
    auto STS = [&](uint32_t Ab, uint32_t Bb) {
        #pragma unroll
        for (int i = 0; i < 4; i++) {
            uint32_t off = lrow[i] * 128 + ((lchk[i] ^ (lrow[i] & 7)) << 4);
            sts128(Ab + off, f2tf(ra[i].x), f2tf(ra[i].y), f2tf(ra[i].z), f2tf(ra[i].w));
            sts128(Bb + off, f2tf(rb[i].x), f2tf(rb[i].y), f2tf(rb[i].z), f2tf(rb[i].w));
        }
    };

    LDG(0); STS(s0, s0 + 16384);
    __syncthreads();

    for (int kt = 0; kt < 32; kt++) {
        const int p = kt & 1;
        if (kt < 31) LDG(kt + 1);
        const uint32_t Ab = s0 + p * 32768, Bb = Ab + 16384;
        #pragma unroll
        for (int ks = 0; ks < 4; ks++) {
            uint32_t a[4][4], b[2][4];
            #pragma unroll
            for (int mi = 0; mi < 4; mi++)
                ldsm4(a[mi], Ab + (wm*64 + mi*16 + arow) * 128 + (((ks*2 + ahi) ^ rx) << 4));
            #pragma unroll
            for (int pr = 0; pr < 2; pr++)
                ldsm4(b[pr], Bb + (wn*32 + pr*16 + brow) * 128 + (((ks*2 + bhi) ^ rx) << 4));
            #pragma unroll
            for (int mi = 0; mi < 4; mi++)
                #pragma unroll
                for (int ni = 0; ni < 4; ni++)
                    mma8(acc[mi][ni], a[mi], b[ni>>1][(ni&1)*2], b[ni>>1][(ni&1)*2+1]);
        }
        if (kt < 31) STS(s0 + (1-p) * 32768, s0 + (1-p) * 32768 + 16384);
        __syncthreads();
    }

    const int part = n0 >> 10;
    if (part < 2) {
        #pragma unroll
        for (int mi = 0; mi < 4; mi++) {
            #pragma unroll
            for (int half = 0; half < 2; half++) {
                const int m = m0 + wm*64 + mi*16 + (lane >> 2) + half*8;
                const int bb = m >> 11, t = m & 2047;
                #pragma unroll
                for (int ni = 0; ni < 4; ni++) {
                    const int n = n0 + wn*32 + ni*8 + 2*(lane & 3);
                    const int hh = (n >> 6) & 15, d = n & 63;
                    const float v0 = __uint_as_float(f2tf(acc[mi][ni][half*2+0] + __ldg(bias + n)));
                    const float v1 = __uint_as_float(f2tf(acc[mi][ni][half*2+1] + __ldg(bias + n + 1)));
                    float* dst = (part == 0 ? g_q : g_k) + (((size_t)(bb*H_ + hh) * T_ + t) * D_ + d);
                    *(float2*)dst = make_float2(v0, v1);
                }
            }
        }
    } else {
        float* sv = (float*)smem;
        #pragma unroll
        for (int mi = 0; mi < 4; mi++) {
            #pragma unroll
            for (int half = 0; half < 2; half++) {
                const int ml = wm*64 + mi*16 + (lane >> 2) + half*8;
                #pragma unroll
                for (int ni = 0; ni < 4; ni++) {
                    const int nl = wn*32 + ni*8 + 2*(lane & 3);
                    const int n = n0 + nl;
                    sv[(nl    ) * 132 + ml] = __uint_as_float(f2tf(acc[mi][ni][half*2+0] + __ldg(bias + n)));
                    sv[(nl + 1) * 132 + ml] = __uint_as_float(f2tf(acc[mi][ni][half*2+1] + __ldg(bias + n + 1)));
                }
            }
        }
        __syncthreads();
        const int hh = (n0 & 1023) >> 6;
        const int bb = m0 >> 11, t0 = m0 & 2047;
        #pragma unroll
        for (int i = 0; i < 16; i++) {
            const int idx = tid + 256 * i;
            const int row = idx >> 5, ch = idx & 31;
            float4 v = *(const float4*)(sv + row * 132 + ch * 4);
            const int h = hh + (row >> 6), d = row & 63;
            *(float4*)(g_vt + ((size_t)(bb*H_ + h) * D_ + d) * T_ + t0 + ch * 4) = v;
        }
    }
}

// ---------------------------------------------------------------------------
// Kernel 2: Y = relu(Q K^T * scale, causal) @ V — S kept in REGISTERS.
// K-tile rows stored row-permuted (key k -> row 2k | 2(k-4)+1 within 8-groups)
// so MMA1's C-fragment is directly MMA2's A-fragment via renaming (c0,c2,c1,c3).
// Warps 4m x 2n (warp tile 32x64); each warp owns a 64-key strip; partial Y
// reduced pairwise through smem once after the key loop. 1 sync per key tile.
// ---------------------------------------------------------------------------
__global__ __launch_bounds__(256) void attn_mma_kernel(float* __restrict__ out)
{
    extern __shared__ __align__(1024) char smem[];
    const uint32_t s0 = smem_u32(smem);
    const uint32_t Qs = s0;                                 // 32KB (reused for Y reduce)
    const uint32_t Kst[2] = { s0 + 32768,  s0 + 98304  };   // 32KB each
    const uint32_t Vst[2] = { s0 + 65536,  s0 + 131072 };   // 32KB each; total 160KB

    const int tid = threadIdx.x, lane = tid & 31, wid = tid >> 5;
    const int wm = wid >> 1, wn = wid & 1;                  // 4m x 2n
    const int qt = (int)(gridDim.x - 1) - (int)blockIdx.x;  // LPT order
    const int h = blockIdx.y, bb = blockIdx.z;
    const int q0 = qt * 128;
    const size_t bh = (size_t)(bb * H_ + h);
    const float* Qg  = g_q  + bh * T_ * D_;
    const float* Kg  = g_k  + bh * T_ * D_;
    const float* Vtg = g_vt + bh * (size_t)D_ * T_;

    const int rx   = lane & 7;
    const int arow = (lane & 7) + ((lane >> 3) & 1) * 8;
    const int ahi  = lane >> 4;
    const int brow = (lane & 7) + ((lane >> 4) << 3);
    const int bhi  = (lane >> 3) & 1;

    auto loadKV = [&](int jt, int st) {
        const int j0 = jt * 128;
        #pragma unroll
        for (int i = 0; i < 8; i++) {           // K: 128 keys x 64 d, rows sigma-permuted
            int s = tid + 256 * i, row = s >> 4, c = s & 15;
            int prow = (row & ~7) | (((row & 3) << 1) | ((row & 7) >> 2));
            cp16(Kst[st] + prow * 256 + ((c ^ (prow & 7)) << 4),
                 Kg + (size_t)(j0 + row) * D_ + c * 4);
        }
        #pragma unroll
        for (int i = 0; i < 8; i++) {           // Vt: 64 d x 128 keys (natural)
            int s = tid + 256 * i, row = s >> 5, c = s & 31;
            cp16(Vst[st] + row * 512 + ((c ^ (row & 7)) << 4),
                 Vtg + (size_t)row * T_ + j0 + c * 4);
        }
    };

    // Prologue: Q + KV(0) in one cp.async group.
    #pragma unroll
    for (int i = 0; i < 8; i++) {
        int s = tid + 256 * i, row = s >> 4, c = s & 15;
        cp16(Qs + row * 256 + ((c ^ (row & 7)) << 4),
             Qg + (size_t)(q0 + row) * D_ + c * 4);
    }
    loadKV(0, 0);
    cp_commit();

    float accY[2][8][4] = {};

    for (int jt = 0; jt <= qt; jt++) {
        const int p = jt & 1;
        const int j0 = jt * 128;
        cp_wait0();
        __syncthreads();                         // buf[p] ready; all warps done with buf[1-p]
        if (jt < qt) { loadKV(jt + 1, 1 - p); cp_commit(); }

        // MMA1: S = Q @ K^T   (warp tile 32m x 64n, K=64 -> 8 k-steps)
        float accS[2][8][4] = {};
        #pragma unroll
        for (int ks = 0; ks < 8; ks++) {
            uint32_t a[2][4], b[4][4];
            #pragma unroll
            for (int mi = 0; mi < 2; mi++)
                ldsm4(a[mi], Qs + (wm*32 + mi*16 + arow) * 256 + (((ks*2 + ahi) ^ rx) << 4));
            #pragma unroll
            for (int pr = 0; pr < 4; pr++)
                ldsm4(b[pr], Kst[p] + (wn*64 + pr*16 + brow) * 256 + (((ks*2 + bhi) ^ rx) << 4));
            #pragma unroll
            for (int mi = 0; mi < 2; mi++)
                #pragma unroll
                for (int ni = 0; ni < 8; ni++)
                    mma8(accS[mi][ni], a[mi], b[ni>>1][(ni&1)*2], b[ni>>1][(ni&1)*2+1]);
        }

        // In-register epilogue: scale + ReLU (+ causal mask on diagonal tile) + tf32.
        // Logical keys: regs {0,2} -> j0+wn*64+ni*8+(lane&3); regs {1,3} -> +4.
        uint32_t sf[2][8][4];
        if (jt == qt) {
            #pragma unroll
            for (int mi = 0; mi < 2; mi++) {
                const int r0 = q0 + wm*32 + mi*16 + (lane >> 2);
                #pragma unroll
                for (int ni = 0; ni < 8; ni++) {
                    const int k0 = j0 + wn*64 + ni*8 + (lane & 3);
                    float v0 = accS[mi][ni][0] * 0.125f;
                    float v1 = accS[mi][ni][1] * 0.125f;
                    float v2 = accS[mi][ni][2] * 0.125f;
                    float v3 = accS[mi][ni][3] * 0.125f;
                    v0 = (v0 > 0.f && k0     <= r0    ) ? v0 : 0.f;
                    v1 = (v1 > 0.f && k0 + 4 <= r0    ) ? v1 : 0.f;
                    v2 = (v2 > 0.f && k0     <= r0 + 8) ? v2 : 0.f;
                    v3 = (v3 > 0.f && k0 + 4 <= r0 + 8) ? v3 : 0.f;
                    sf[mi][ni][0] = f2tf(v0); sf[mi][ni][1] = f2tf(v1);
                    sf[mi][ni][2] = f2tf(v2); sf[mi][ni][3] = f2tf(v3);
                }
            }
        } else {
            #pragma unroll
            for (int mi = 0; mi < 2; mi++)
                #pragma unroll
                for (int ni = 0; ni < 8; ni++)
                    #pragma unroll
                    for (int e = 0; e < 4; e++) {
                        float v = accS[mi][ni][e] * 0.125f;
                        sf[mi][ni][e] = f2tf(v > 0.f ? v : 0.f);
                    }
        }

        // MMA2: Y += S @ V over this warp's 64-key strip (8 k-steps).
        // A-fragment = renamed S regs (c0,c2,c1,c3). B = V, natural key order.
        #pragma unroll
        for (int ks = 0; ks < 8; ks++) {
            uint32_t b[4][4];
            #pragma unroll
            for (int pr = 0; pr < 4; pr++)
                ldsm4(b[pr], Vst[p] + (pr*16 + brow) * 512 + (((wn*16 + ks*2 + bhi) ^ rx) << 4));
            #pragma unroll
            for (int mi = 0; mi < 2; mi++)
                #pragma unroll
                for (int ni = 0; ni < 8; ni++)
                    mma8u(accY[mi][ni],
                          sf[mi][ks][0], sf[mi][ks][2], sf[mi][ks][1], sf[mi][ks][3],
                          b[ni>>1][(ni&1)*2], b[ni>>1][(ni&1)*2+1]);
        }
    }

    // Cross-warp pairwise reduce (wn=1 -> smem, wn=0 adds + stores to gmem).
    __syncthreads();                             // all warps done reading K/V/Q smem
    float* red = (float*)smem;                   // reuse Qs region: 128 rows x pitch 65
    if (wn == 1) {
        #pragma unroll
        for (int mi = 0; mi < 2; mi++)
            #pragma unroll
            for (int half = 0; half < 2; half++) {
                const int r = wm*32 + mi*16 + half*8 + (lane >> 2);
                #pragma unroll
                for (int ni = 0; ni < 8; ni++) {
                    red[r * 65 + ni*8 + 2*(lane & 3)    ] = accY[mi][ni][half*2+0];
                    red[r * 65 + ni*8 + 2*(lane & 3) + 1] = accY[mi][ni][half*2+1];
                }
            }
    }
    __syncthreads();
    if (wn == 0) {
        #pragma unroll
        for (int mi = 0; mi < 2; mi++)
            #pragma unroll
            for (int half = 0; half < 2; half++) {
                const int r = wm*32 + mi*16 + half*8 + (lane >> 2);
                const int t = q0 + r;
                float* orow = out + ((size_t)bb * T_ + t) * C_ + h * D_;
                #pragma unroll
                for (int ni = 0; ni < 8; ni++) {
                    const int d = ni*8 + 2*(lane & 3);
                    float v0 = accY[mi][ni][half*2+0] + red[r * 65 + d];
                    float v1 = accY[mi][ni][half*2+1] + red[r * 65 + d + 1];
                    *(float2*)(orow + d) = make_float2(v0, v1);
                }
            }
    }
}

extern "C" void kernel_launch(void* const* d_in, const int* in_sizes, int n_in,
                              void* d_out, int out_size)
{
    const float* x    = (const float*)d_in[0];
    const float* W    = (const float*)d_in[1];
    const float* bias = (const float*)d_in[2];
    float* out = (float*)d_out;

    const int qkv_smem  = 67584;
    const int attn_smem = 163840;   // Q32K + 2x(K32K+V32K)
    cudaFuncSetAttribute(qkv_mma_kernel,  cudaFuncAttributeMaxDynamicSharedMemorySize, qkv_smem);
    cudaFuncSetAttribute(attn_mma_kernel, cudaFuncAttributeMaxDynamicSharedMemorySize, attn_smem);

    dim3 g1(24, 32);
    qkv_mma_kernel<<<g1, 256, qkv_smem>>>(x, W, bias);

    dim3 g2(16, 16, 2);
    attn_mma_kernel<<<g2, 256, attn_smem>>>(out);
}

// round 6
// speedup vs baseline: 4.9207x; 1.0502x over previous
#include <cuda_runtime.h>
#include <cstdint>

#define B_ 2
#define T_ 2048
#define C_ 1024
#define H_ 16
#define D_ 64
#define M_ (B_*T_)
#define N3_ (3*C_)

// Scratch (tf32-rounded values): Q,K in [b,h,t,d]; V transposed in [b,h,d,t].
__device__ float g_q [B_*H_*T_*D_];
__device__ float g_k [B_*H_*T_*D_];
__device__ float g_vt[B_*H_*D_*T_];
// tf32-pre-rounded copies of x and W (lets qkv GEMM use cp.async, no cvt in loop)
__device__ float g_x [M_*C_];
__device__ float g_w [N3_*C_];

// ---------------------------------------------------------------------------
// helpers (all base sm_80 PTX — legal on compute_103 family target)
// ---------------------------------------------------------------------------
__device__ __forceinline__ uint32_t smem_u32(const void* p){
    uint32_t a;
    asm("{ .reg .u64 t; cvta.to.shared.u64 t, %1; cvt.u32.u64 %0, t; }" : "=r"(a) : "l"(p));
    return a;
}
__device__ __forceinline__ uint32_t f2tf(float f){
    uint32_t r; asm("cvt.rna.tf32.f32 %0, %1;" : "=r"(r) : "f"(f)); return r;
}
__device__ __forceinline__ void ldsm4(uint32_t (&r)[4], uint32_t a){
    asm volatile("ldmatrix.sync.aligned.m8n8.x4.shared.b16 {%0,%1,%2,%3}, [%4];"
        : "=r"(r[0]), "=r"(r[1]), "=r"(r[2]), "=r"(r[3]) : "r"(a));
}
__device__ __forceinline__ void mma8(float (&d)[4], const uint32_t (&a)[4], uint32_t b0, uint32_t b1){
    asm volatile("mma.sync.aligned.m16n8k8.row.col.f32.tf32.tf32.f32 "
        "{%0,%1,%2,%3}, {%4,%5,%6,%7}, {%8,%9}, {%0,%1,%2,%3};"
        : "+f"(d[0]), "+f"(d[1]), "+f"(d[2]), "+f"(d[3])
        : "r"(a[0]), "r"(a[1]), "r"(a[2]), "r"(a[3]), "r"(b0), "r"(b1));
}
__device__ __forceinline__ void mma8u(float (&d)[4], uint32_t a0, uint32_t a1, uint32_t a2, uint32_t a3,
                                      uint32_t b0, uint32_t b1){
    asm volatile("mma.sync.aligned.m16n8k8.row.col.f32.tf32.tf32.f32 "
        "{%0,%1,%2,%3}, {%4,%5,%6,%7}, {%8,%9}, {%0,%1,%2,%3};"
        : "+f"(d[0]), "+f"(d[1]), "+f"(d[2]), "+f"(d[3])
        : "r"(a0), "r"(a1), "r"(a2), "r"(a3), "r"(b0), "r"(b1));
}
__device__ __forceinline__ void cp16(uint32_t dst, const void* src){
    asm volatile("cp.async.ca.shared.global [%0], [%1], 16;" :: "r"(dst), "l"(src) : "memory");
}
__device__ __forceinline__ void cp_commit(){ asm volatile("cp.async.commit_group;" ::: "memory"); }
__device__ __forceinline__ void cp_wait0(){ asm volatile("cp.async.wait_group 0;" ::: "memory"); }
__device__ __forceinline__ void cp_wait1(){ asm volatile("cp.async.wait_group 1;" ::: "memory"); }

// ---------------------------------------------------------------------------
// Kernel 0: tf32-round x and W into g_x, g_w (elementwise, float4).
// ---------------------------------------------------------------------------
#define NX4_ (M_*C_/4)
#define NW4_ (N3_*C_/4)
__global__ __launch_bounds__(256) void round_kernel(
    const float* __restrict__ x, const float* __restrict__ W)
{
    const int i = blockIdx.x * 256 + threadIdx.x;
    if (i < NX4_) {
        float4 v = __ldg((const float4*)x + i);
        v.x = __uint_as_float(f2tf(v.x)); v.y = __uint_as_float(f2tf(v.y));
        v.z = __uint_as_float(f2tf(v.z)); v.w = __uint_as_float(f2tf(v.w));
        ((float4*)g_x)[i] = v;
    } else if (i < NX4_ + NW4_) {
        const int j = i - NX4_;
        float4 v = __ldg((const float4*)W + j);
        v.x = __uint_as_float(f2tf(v.x)); v.y = __uint_as_float(f2tf(v.y));
        v.z = __uint_as_float(f2tf(v.z)); v.w = __uint_as_float(f2tf(v.w));
        ((float4*)g_w)[j] = v;
    }
}

// ---------------------------------------------------------------------------
// Kernel 1: QKV = g_x @ g_w^T + b  (M=4096, N=3072, K=1024), tf32 mma.sync.
// cp.async 3-stage pipeline, no register staging / no cvt in loop -> <=128
// regs -> 2 CTAs/SM. Epilogue: Q,K -> [b,h,t,d]; V -> smem transpose -> [b,h,d,t].
// ---------------------------------------------------------------------------
__global__ void __launch_bounds__(256, 2) qkv_mma_kernel(const float* __restrict__ bias)
{
    extern __shared__ __align__(1024) char smem[];
    const uint32_t s0 = smem_u32(smem);           // 3 stages x (A16K + B16K)
    const int tid = threadIdx.x, lane = tid & 31, wid = tid >> 5;
    const int wm = wid >> 2, wn = wid & 3;
    const int m0 = blockIdx.y * 128, n0 = blockIdx.x * 128;

    const int rx   = lane & 7;
    const int arow = (lane & 7) + ((lane >> 3) & 1) * 8;
    const int ahi  = lane >> 4;
    const int brow = (lane & 7) + ((lane >> 4) << 3);
    const int bhi  = (lane >> 3) & 1;

    auto loadAB = [&](int kt, int st) {
        const uint32_t Ab = s0 + st * 32768, Bb = Ab + 16384;
        #pragma unroll
        for (int i = 0; i < 4; i++) {
            const int s = tid + 256 * i, row = s >> 3, c = s & 7;
            const uint32_t off = row * 128 + ((c ^ (row & 7)) << 4);
            cp16(Ab + off, g_x + (size_t)(m0 + row) * C_ + kt * 32 + c * 4);
            cp16(Bb + off, g_w + (size_t)(n0 + row) * C_ + kt * 32 + c * 4);
        }
    };

    float acc[4][4][4] = {};

    loadAB(0, 0); cp_commit();
    loadAB(1, 1); cp_commit();

    for (int kt = 0; kt < 32; kt++) {
        if (kt < 31) cp_wait1(); else cp_wait0();
        __syncthreads();
        if (kt + 2 < 32) { loadAB(kt + 2, (kt + 2) % 3); cp_commit(); }

        const uint32_t Ab = s0 + (kt % 3) * 32768, Bb = Ab + 16384;
        #pragma unroll
        for (int ks = 0; ks < 4; ks++) {
            uint32_t a[4][4], b[2][4];
            #pragma unroll
            for (int mi = 0; mi < 4; mi++)
                ldsm4(a[mi], Ab + (wm*64 + mi*16 + arow) * 128 + (((ks*2 + ahi) ^ rx) << 4));
            #pragma unroll
            for (int pr = 0; pr < 2; pr++)
                ldsm4(b[pr], Bb + (wn*32 + pr*16 + brow) * 128 + (((ks*2 + bhi) ^ rx) << 4));
            #pragma unroll
            for (int mi = 0; mi < 4; mi++)
                #pragma unroll
                for (int ni = 0; ni < 4; ni++)
                    mma8(acc[mi][ni], a[mi], b[ni>>1][(ni&1)*2], b[ni>>1][(ni&1)*2+1]);
        }
        __syncthreads();
    }

    const int part = n0 >> 10;   // whole CTA tile lies in one of q/k/v
    if (part < 2) {
        #pragma unroll
        for (int mi = 0; mi < 4; mi++) {
            #pragma unroll
            for (int half = 0; half < 2; half++) {
                const int m = m0 + wm*64 + mi*16 + (lane >> 2) + half*8;
                const int bb = m >> 11, t = m & 2047;
                #pragma unroll
                for (int ni = 0; ni < 4; ni++) {
                    const int n = n0 + wn*32 + ni*8 + 2*(lane & 3);
                    const int hh = (n >> 6) & 15, d = n & 63;
                    const float v0 = __uint_as_float(f2tf(acc[mi][ni][half*2+0] + __ldg(bias + n)));
                    const float v1 = __uint_as_float(f2tf(acc[mi][ni][half*2+1] + __ldg(bias + n + 1)));
                    float* dst = (part == 0 ? g_q : g_k) + (((size_t)(bb*H_ + hh) * T_ + t) * D_ + d);
                    *(float2*)dst = make_float2(v0, v1);
                }
            }
        }
    } else {
        float* sv = (float*)smem;
        #pragma unroll
        for (int mi = 0; mi < 4; mi++) {
            #pragma unroll
            for (int half = 0; half < 2; half++) {
                const int ml = wm*64 + mi*16 + (lane >> 2) + half*8;
                #pragma unroll
                for (int ni = 0; ni < 4; ni++) {
                    const int nl = wn*32 + ni*8 + 2*(lane & 3);
                    const int n = n0 + nl;
                    sv[(nl    ) * 132 + ml] = __uint_as_float(f2tf(acc[mi][ni][half*2+0] + __ldg(bias + n)));
                    sv[(nl + 1) * 132 + ml] = __uint_as_float(f2tf(acc[mi][ni][half*2+1] + __ldg(bias + n + 1)));
                }
            }
        }
        __syncthreads();
        const int hh = (n0 & 1023) >> 6;
        const int bb = m0 >> 11, t0 = m0 & 2047;
        #pragma unroll
        for (int i = 0; i < 16; i++) {
            const int idx = tid + 256 * i;
            const int row = idx >> 5, ch = idx & 31;
            float4 v = *(const float4*)(sv + row * 132 + ch * 4);
            const int h = hh + (row >> 6), d = row & 63;
            *(float4*)(g_vt + ((size_t)(bb*H_ + h) * D_ + d) * T_ + t0 + ch * 4) = v;
        }
    }
}

// ---------------------------------------------------------------------------
// Kernel 2: Y = relu(Q K^T * scale, causal) @ V — S in registers (unchanged R5).
// ---------------------------------------------------------------------------
__global__ __launch_bounds__(256) void attn_mma_kernel(float* __restrict__ out)
{
    extern __shared__ __align__(1024) char smem[];
    const uint32_t s0 = smem_u32(smem);
    const uint32_t Qs = s0;
    const uint32_t Kst[2] = { s0 + 32768,  s0 + 98304  };
    const uint32_t Vst[2] = { s0 + 65536,  s0 + 131072 };

    const int tid = threadIdx.x, lane = tid & 31, wid = tid >> 5;
    const int wm = wid >> 1, wn = wid & 1;
    const int qt = (int)(gridDim.x - 1) - (int)blockIdx.x;
    const int h = blockIdx.y, bb = blockIdx.z;
    const int q0 = qt * 128;
    const size_t bh = (size_t)(bb * H_ + h);
    const float* Qg  = g_q  + bh * T_ * D_;
    const float* Kg  = g_k  + bh * T_ * D_;
    const float* Vtg = g_vt + bh * (size_t)D_ * T_;

    const int rx   = lane & 7;
    const int arow = (lane & 7) + ((lane >> 3) & 1) * 8;
    const int ahi  = lane >> 4;
    const int brow = (lane & 7) + ((lane >> 4) << 3);
    const int bhi  = (lane >> 3) & 1;

    auto loadKV = [&](int jt, int st) {
        const int j0 = jt * 128;
        #pragma unroll
        for (int i = 0; i < 8; i++) {
            int s = tid + 256 * i, row = s >> 4, c = s & 15;
            int prow = (row & ~7) | (((row & 3) << 1) | ((row & 7) >> 2));
            cp16(Kst[st] + prow * 256 + ((c ^ (prow & 7)) << 4),
                 Kg + (size_t)(j0 + row) * D_ + c * 4);
        }
        #pragma unroll
        for (int i = 0; i < 8; i++) {
            int s = tid + 256 * i, row = s >> 5, c = s & 31;
            cp16(Vst[st] + row * 512 + ((c ^ (row & 7)) << 4),
                 Vtg + (size_t)row * T_ + j0 + c * 4);
        }
    };

    #pragma unroll
    for (int i = 0; i < 8; i++) {
        int s = tid + 256 * i, row = s >> 4, c = s & 15;
        cp16(Qs + row * 256 + ((c ^ (row & 7)) << 4),
             Qg + (size_t)(q0 + row) * D_ + c * 4);
    }
    loadKV(0, 0);
    cp_commit();

    float accY[2][8][4] = {};

    for (int jt = 0; jt <= qt; jt++) {
        const int p = jt & 1;
        const int j0 = jt * 128;
        cp_wait0();
        __syncthreads();
        if (jt < qt) { loadKV(jt + 1, 1 - p); cp_commit(); }

        float accS[2][8][4] = {};
        #pragma unroll
        for (int ks = 0; ks < 8; ks++) {
            uint32_t a[2][4], b[4][4];
            #pragma unroll
            for (int mi = 0; mi < 2; mi++)
                ldsm4(a[mi], Qs + (wm*32 + mi*16 + arow) * 256 + (((ks*2 + ahi) ^ rx) << 4));
            #pragma unroll
            for (int pr = 0; pr < 4; pr++)
                ldsm4(b[pr], Kst[p] + (wn*64 + pr*16 + brow) * 256 + (((ks*2 + bhi) ^ rx) << 4));
            #pragma unroll
            for (int mi = 0; mi < 2; mi++)
                #pragma unroll
                for (int ni = 0; ni < 8; ni++)
                    mma8(accS[mi][ni], a[mi], b[ni>>1][(ni&1)*2], b[ni>>1][(ni&1)*2+1]);
        }

        uint32_t sf[2][8][4];
        if (jt == qt) {
            #pragma unroll
            for (int mi = 0; mi < 2; mi++) {
                const int r0 = q0 + wm*32 + mi*16 + (lane >> 2);
                #pragma unroll
                for (int ni = 0; ni < 8; ni++) {
                    const int k0 = j0 + wn*64 + ni*8 + (lane & 3);
                    float v0 = accS[mi][ni][0] * 0.125f;
                    float v1 = accS[mi][ni][1] * 0.125f;
                    float v2 = accS[mi][ni][2] * 0.125f;
                    float v3 = accS[mi][ni][3] * 0.125f;
                    v0 = (v0 > 0.f && k0     <= r0    ) ? v0 : 0.f;
                    v1 = (v1 > 0.f && k0 + 4 <= r0    ) ? v1 : 0.f;
                    v2 = (v2 > 0.f && k0     <= r0 + 8) ? v2 : 0.f;
                    v3 = (v3 > 0.f && k0 + 4 <= r0 + 8) ? v3 : 0.f;
                    sf[mi][ni][0] = f2tf(v0); sf[mi][ni][1] = f2tf(v1);
                    sf[mi][ni][2] = f2tf(v2); sf[mi][ni][3] = f2tf(v3);
                }
            }
        } else {
            #pragma unroll
            for (int mi = 0; mi < 2; mi++)
                #pragma unroll
                for (int ni = 0; ni < 8; ni++)
                    #pragma unroll
                    for (int e = 0; e < 4; e++) {
                        float v = accS[mi][ni][e] * 0.125f;
                        sf[mi][ni][e] = f2tf(v > 0.f ? v : 0.f);
                    }
        }

        #pragma unroll
        for (int ks = 0; ks < 8; ks++) {
            uint32_t b[4][4];
            #pragma unroll
            for (int pr = 0; pr < 4; pr++)
                ldsm4(b[pr], Vst[p] + (pr*16 + brow) * 512 + (((wn*16 + ks*2 + bhi) ^ rx) << 4));
            #pragma unroll
            for (int mi = 0; mi < 2; mi++)
                #pragma unroll
                for (int ni = 0; ni < 8; ni++)
                    mma8u(accY[mi][ni],
                          sf[mi][ks][0], sf[mi][ks][2], sf[mi][ks][1], sf[mi][ks][3],
                          b[ni>>1][(ni&1)*2], b[ni>>1][(ni&1)*2+1]);
        }
    }

    __syncthreads();
    float* red = (float*)smem;
    if (wn == 1) {
        #pragma unroll
        for (int mi = 0; mi < 2; mi++)
            #pragma unroll
            for (int half = 0; half < 2; half++) {
                const int r = wm*32 + mi*16 + half*8 + (lane >> 2);
                #pragma unroll
                for (int ni = 0; ni < 8; ni++) {
                    red[r * 65 + ni*8 + 2*(lane & 3)    ] = accY[mi][ni][half*2+0];
                    red[r * 65 + ni*8 + 2*(lane & 3) + 1] = accY[mi][ni][half*2+1];
                }
            }
    }
    __syncthreads();
    if (wn == 0) {
        #pragma unroll
        for (int mi = 0; mi < 2; mi++)
            #pragma unroll
            for (int half = 0; half < 2; half++) {
                const int r = wm*32 + mi*16 + half*8 + (lane >> 2);
                const int t = q0 + r;
                float* orow = out + ((size_t)bb * T_ + t) * C_ + h * D_;
                #pragma unroll
                for (int ni = 0; ni < 8; ni++) {
                    const int d = ni*8 + 2*(lane & 3);
                    float v0 = accY[mi][ni][half*2+0] + red[r * 65 + d];
                    float v1 = accY[mi][ni][half*2+1] + red[r * 65 + d + 1];
                    *(float2*)(orow + d) = make_float2(v0, v1);
                }
            }
    }
}

extern "C" void kernel_launch(void* const* d_in, const int* in_sizes, int n_in,
                              void* d_out, int out_size)
{
    const float* x    = (const float*)d_in[0];
    const float* W    = (const float*)d_in[1];
    const float* bias = (const float*)d_in[2];
    float* out = (float*)d_out;

    const int qkv_smem  = 98304;    // 3 stages x 32KB (>= 67584B transpose scratch)
    const int attn_smem = 163840;   // Q32K + 2x(K32K+V32K)
    cudaFuncSetAttribute(qkv_mma_kernel,  cudaFuncAttributeMaxDynamicSharedMemorySize, qkv_smem);
    cudaFuncSetAttribute(attn_mma_kernel, cudaFuncAttributeMaxDynamicSharedMemorySize, attn_smem);

    const int nElem4 = NX4_ + NW4_;
    round_kernel<<<(nElem4 + 255) / 256, 256>>>(x, W);

    dim3 g1(24, 32);
    qkv_mma_kernel<<<g1, 256, qkv_smem>>>(bias);

    dim3 g2(16, 16, 2);
    attn_mma_kernel<<<g2, 256, attn_smem>>>(out);
}

// round 8
// speedup vs baseline: 7.8316x; 1.5916x over previous
#include <cuda_runtime.h>
#include <cuda_fp16.h>
#include <cstdint>

#define B_ 2
#define T_ 2048
#define C_ 1024
#define H_ 16
#define D_ 64
#define M_ (B_*T_)
#define N3_ (3*C_)

// Scratch (fp16 values): Q,K in [b,h,t,d]; V transposed in [b,h,d,t].
__device__ __half g_q [B_*H_*T_*D_];
__device__ __half g_k [B_*H_*T_*D_];
__device__ __half g_vt[B_*H_*D_*T_];
// fp16 copies of x and W
__device__ __half g_x [M_*C_];
__device__ __half g_w [N3_*C_];

// ---------------------------------------------------------------------------
// helpers (base sm_80 PTX)
// ---------------------------------------------------------------------------
__device__ __forceinline__ uint32_t smem_u32(const void* p){
    uint32_t a;
    asm("{ .reg .u64 t; cvta.to.shared.u64 t, %1; cvt.u32.u64 %0, t; }" : "=r"(a) : "l"(p));
    return a;
}
__device__ __forceinline__ uint32_t pack2(float x, float y){
    __half2 h = __floats2half2_rn(x, y);
    return *(uint32_t*)&h;
}
__device__ __forceinline__ void ldsm4(uint32_t (&r)[4], uint32_t a){
    asm volatile("ldmatrix.sync.aligned.m8n8.x4.shared.b16 {%0,%1,%2,%3}, [%4];"
        : "=r"(r[0]), "=r"(r[1]), "=r"(r[2]), "=r"(r[3]) : "r"(a));
}
__device__ __forceinline__ void mma16(float (&d)[4], uint32_t a0, uint32_t a1, uint32_t a2, uint32_t a3,
                                      uint32_t b0, uint32_t b1){
    asm volatile("mma.sync.aligned.m16n8k16.row.col.f32.f16.f16.f32 "
        "{%0,%1,%2,%3}, {%4,%5,%6,%7}, {%8,%9}, {%0,%1,%2,%3};"
        : "+f"(d[0]), "+f"(d[1]), "+f"(d[2]), "+f"(d[3])
        : "r"(a0), "r"(a1), "r"(a2), "r"(a3), "r"(b0), "r"(b1));
}
__device__ __forceinline__ void cp16(uint32_t dst, const void* src){
    asm volatile("cp.async.ca.shared.global [%0], [%1], 16;" :: "r"(dst), "l"(src) : "memory");
}
__device__ __forceinline__ void cp_commit(){ asm volatile("cp.async.commit_group;" ::: "memory"); }
__device__ __forceinline__ void cp_wait0(){ asm volatile("cp.async.wait_group 0;" ::: "memory"); }
__device__ __forceinline__ void cp_wait1(){ asm volatile("cp.async.wait_group 1;" ::: "memory"); }

// ---------------------------------------------------------------------------
// Kernel 0: fp16-convert x and W into g_x, g_w (8 floats -> 8 halves / thread).
// ---------------------------------------------------------------------------
#define NX8_ (M_*C_/8)
#define NW8_ (N3_*C_/8)
__global__ __launch_bounds__(256) void round_kernel(
    const float* __restrict__ x, const float* __restrict__ W)
{
    const int i = blockIdx.x * 256 + threadIdx.x;
    const float4* src; __half* dst;
    if (i < NX8_)              { src = (const float4*)x + (size_t)i * 2;          dst = g_x + (size_t)i * 8; }
    else if (i < NX8_ + NW8_)  { const int j = i - NX8_;
                                 src = (const float4*)W + (size_t)j * 2;          dst = g_w + (size_t)j * 8; }
    else return;
    float4 v0 = __ldg(src), v1 = __ldg(src + 1);
    uint4 o;
    o.x = pack2(v0.x, v0.y); o.y = pack2(v0.z, v0.w);
    o.z = pack2(v1.x, v1.y); o.w = pack2(v1.z, v1.w);
    *(uint4*)dst = o;
}

// ---------------------------------------------------------------------------
// Kernel 1: QKV = g_x @ g_w^T + b  (M=4096, N=3072, K=1024), fp16 m16n8k16.
// 128x128 CTA tile, BK=64 halves (128B rows), 3-stage cp.async, 2 CTAs/SM.
// ---------------------------------------------------------------------------
__global__ void __launch_bounds__(256, 2) qkv_mma_kernel(const float* __restrict__ bias)
{
    extern __shared__ __align__(1024) char smem[];
    const uint32_t s0 = smem_u32(smem);            // 3 stages x (A16K + B16K)
    const int tid = threadIdx.x, lane = tid & 31, wid = tid >> 5;
    const int wm = wid >> 2, wn = wid & 3;
    const int m0 = blockIdx.y * 128, n0 = blockIdx.x * 128;

    const int lrow = (lane & 7) + ((lane >> 3) & 1) * 8;   // ldmatrix row-within-16
    const int lhi  = lane >> 4;                            // ldmatrix chunk-hi

    auto loadAB = [&](int kt, int st) {
        const uint32_t Ab = s0 + st * 32768, Bb = Ab + 16384;
        #pragma unroll
        for (int i = 0; i < 4; i++) {
            const int s = tid + 256 * i, row = s >> 3, c = s & 7;
            const uint32_t off = row * 128 + ((c ^ (row & 7)) << 4);
            cp16(Ab + off, g_x + (size_t)(m0 + row) * C_ + kt * 64 + c * 8);
            cp16(Bb + off, g_w + (size_t)(n0 + row) * C_ + kt * 64 + c * 8);
        }
    };

    float acc[4][4][4] = {};

    loadAB(0, 0); cp_commit();
    loadAB(1, 1); cp_commit();

    for (int kt = 0; kt < 16; kt++) {
        if (kt < 15) cp_wait1(); else cp_wait0();
        __syncthreads();
        if (kt + 2 < 16) { loadAB(kt + 2, (kt + 2) % 3); cp_commit(); }

        const uint32_t Ab = s0 + (kt % 3) * 32768, Bb = Ab + 16384;
        #pragma unroll
        for (int kk = 0; kk < 4; kk++) {
            uint32_t a[4][4], bm[2][4];
            #pragma unroll
            for (int mi = 0; mi < 4; mi++)
                ldsm4(a[mi], Ab + (wm*64 + mi*16 + lrow) * 128 + (((kk*2 + lhi) ^ (lrow & 7)) << 4));
            #pragma unroll
            for (int pr = 0; pr < 2; pr++)
                ldsm4(bm[pr], Bb + (wn*32 + pr*16 + lrow) * 128 + (((kk*2 + lhi) ^ (lrow & 7)) << 4));
            #pragma unroll
            for (int mi = 0; mi < 4; mi++)
                #pragma unroll
                for (int ni = 0; ni < 4; ni++)
                    mma16(acc[mi][ni], a[mi][0], a[mi][1], a[mi][2], a[mi][3],
                          bm[ni>>1][ni & 1], bm[ni>>1][2 + (ni & 1)]);
        }
        __syncthreads();
    }

    const int part = n0 >> 10;   // whole CTA tile lies in one of q/k/v
    if (part < 2) {
        #pragma unroll
        for (int mi = 0; mi < 4; mi++) {
            #pragma unroll
            for (int half = 0; half < 2; half++) {
                const int m = m0 + wm*64 + mi*16 + (lane >> 2) + half*8;
                const int bb = m >> 11, t = m & 2047;
                #pragma unroll
                for (int ni = 0; ni < 4; ni++) {
                    const int n = n0 + wn*32 + ni*8 + 2*(lane & 3);
                    const int hh = (n >> 6) & 15, d = n & 63;
                    const uint32_t hv = pack2(acc[mi][ni][half*2+0] + __ldg(bias + n),
                                              acc[mi][ni][half*2+1] + __ldg(bias + n + 1));
                    __half* dst = (part == 0 ? g_q : g_k) + (((size_t)(bb*H_ + hh) * T_ + t) * D_ + d);
                    *(uint32_t*)dst = hv;
                }
            }
        }
    } else {
        // V: smem transpose (half, pitch 144) -> coalesced [b,h,d,t].
        __half* sv = (__half*)smem;
        #pragma unroll
        for (int mi = 0; mi < 4; mi++) {
            #pragma unroll
            for (int half = 0; half < 2; half++) {
                const int ml = wm*64 + mi*16 + (lane >> 2) + half*8;
                #pragma unroll
                for (int ni = 0; ni < 4; ni++) {
                    const int nl = wn*32 + ni*8 + 2*(lane & 3);
                    const int n = n0 + nl;
                    sv[(nl    ) * 144 + ml] = __float2half_rn(acc[mi][ni][half*2+0] + __ldg(bias + n));
                    sv[(nl + 1) * 144 + ml] = __float2half_rn(acc[mi][ni][half*2+1] + __ldg(bias + n + 1));
                }
            }
        }
        __syncthreads();
        const int hh = (n0 & 1023) >> 6;
        const int bb = m0 >> 11, t0 = m0 & 2047;
        #pragma unroll
        for (int i = 0; i < 8; i++) {
            const int idx = tid + 256 * i;
            const int row = idx >> 4, ch = idx & 15;     // 128 rows x 16 chunks of 8 halves
            uint4 v = *(const uint4*)(sv + row * 144 + ch * 8);
            const int h = hh + (row >> 6), d = row & 63;
            *(uint4*)(g_vt + ((size_t)(bb*H_ + h) * D_ + d) * T_ + t0 + ch * 8) = v;
        }
    }
}

// ---------------------------------------------------------------------------
// Kernel 2: Y = relu(Q K^T * scale, causal) @ V — fp16 m16n8k16, S in registers.
// MMA1 C-frags pack directly into MMA2 A-frags in NATURAL order (a0,a1,a2,a3).
// Warps 4m x 2n; pairwise Y reduce at end.
// ---------------------------------------------------------------------------
__global__ __launch_bounds__(256) void attn_mma_kernel(float* __restrict__ out)
{
    extern __shared__ __align__(1024) char smem[];
    const uint32_t s0 = smem_u32(smem);
    const uint32_t Qs = s0;                                // 16KB
    const uint32_t Kst[2] = { s0 + 16384, s0 + 49152 };    // 16KB each
    const uint32_t Vst[2] = { s0 + 32768, s0 + 65536 };    // 16KB each; total 80KB

    const int tid = threadIdx.x, lane = tid & 31, wid = tid >> 5;
    const int wm = wid >> 1, wn = wid & 1;                 // 4m x 2n
    const int qt = (int)(gridDim.x - 1) - (int)blockIdx.x; // LPT order
    const int h = blockIdx.y, bb = blockIdx.z;
    const int q0 = qt * 128;
    const size_t bh = (size_t)(bb * H_ + h);
    const __half* Qg  = g_q  + bh * T_ * D_;
    const __half* Kg  = g_k  + bh * T_ * D_;
    const __half* Vtg = g_vt + bh * (size_t)D_ * T_;

    const int lrow = (lane & 7) + ((lane >> 3) & 1) * 8;
    const int lhi  = lane >> 4;

    auto loadKV = [&](int jt, int st) {
        const int j0 = jt * 128;
        #pragma unroll
        for (int i = 0; i < 4; i++) {            // K: 128 keys x 64 d (128B rows)
            int s = tid + 256 * i, row = s >> 3, c = s & 7;
            cp16(Kst[st] + row * 128 + ((c ^ (row & 7)) << 4),
                 Kg + (size_t)(j0 + row) * D_ + c * 8);
        }
        #pragma unroll
        for (int i = 0; i < 4; i++) {            // Vt: 64 d x 128 keys (256B rows)
            int s = tid + 256 * i, row = s >> 4, c = s & 15;
            cp16(Vst[st] + row * 256 + ((c ^ (row & 7)) << 4),
                 Vtg + (size_t)row * T_ + j0 + c * 8);
        }
    };

    // Prologue: Q + KV(0).
    #pragma unroll
    for (int i = 0; i < 4; i++) {
        int s = tid + 256 * i, row = s >> 3, c = s & 7;
        cp16(Qs + row * 128 + ((c ^ (row & 7)) << 4),
             Qg + (size_t)(q0 + row) * D_ + c * 8);
    }
    loadKV(0, 0);
    cp_commit();

    float accY[2][8][4] = {};

    for (int jt = 0; jt <= qt; jt++) {
        const int p = jt & 1;
        const int j0 = jt * 128;
        cp_wait0();
        __syncthreads();
        if (jt < qt) { loadKV(jt + 1, 1 - p); cp_commit(); }

        // MMA1: S = Q @ K^T  (warp 32m x 64keys, K=64 -> 4 k16-steps)
        float accS[2][8][4] = {};
        #pragma unroll
        for (int kk = 0; kk < 4; kk++) {
            uint32_t a[2][4], bm[4][4];
            #pragma unroll
            for (int mi = 0; mi < 2; mi++)
                ldsm4(a[mi], Qs + (wm*32 + mi*16 + lrow) * 128 + (((kk*2 + lhi) ^ (lrow & 7)) << 4));
            #pragma unroll
            for (int pr = 0; pr < 4; pr++)
                ldsm4(bm[pr], Kst[p] + (wn*64 + pr*16 + lrow) * 128 + (((kk*2 + lhi) ^ (lrow & 7)) << 4));
            #pragma unroll
            for (int mi = 0; mi < 2; mi++)
                #pragma unroll
                for (int ni = 0; ni < 8; ni++)
                    mma16(accS[mi][ni], a[mi][0], a[mi][1], a[mi][2], a[mi][3],
                          bm[ni>>1][ni & 1], bm[ni>>1][2 + (ni & 1)]);
        }

        // scale + ReLU (+ causal on diagonal tile) -> pack to fp16 A-frags.
        // sf[mi][kk][0..3] = (a0,a1,a2,a3) for k16-step kk, from S n-tiles 2kk, 2kk+1.
        uint32_t sf[2][4][4];
        #pragma unroll
        for (int mi = 0; mi < 2; mi++) {
            const int r0 = q0 + wm*32 + mi*16 + (lane >> 2);
            #pragma unroll
            for (int kk = 0; kk < 4; kk++) {
                #pragma unroll
                for (int half = 0; half < 2; half++) {
                    const int ni = kk*2 + half;
                    float v0 = accS[mi][ni][0] * 0.125f;
                    float v1 = accS[mi][ni][1] * 0.125f;
                    float v2 = accS[mi][ni][2] * 0.125f;
                    float v3 = accS[mi][ni][3] * 0.125f;
                    if (jt == qt) {
                        const int k0 = j0 + wn*64 + ni*8 + 2*(lane & 3);
                        v0 = (k0     <= r0    ) ? v0 : 0.f;
                        v1 = (k0 + 1 <= r0    ) ? v1 : 0.f;
                        v2 = (k0     <= r0 + 8) ? v2 : 0.f;
                        v3 = (k0 + 1 <= r0 + 8) ? v3 : 0.f;
                    }
                    v0 = v0 > 0.f ? v0 : 0.f;  v1 = v1 > 0.f ? v1 : 0.f;
                    v2 = v2 > 0.f ? v2 : 0.f;  v3 = v3 > 0.f ? v3 : 0.f;
                    sf[mi][kk][half*2 + 0] = pack2(v0, v1);   // (r, k)|(r, k+1)
                    sf[mi][kk][half*2 + 1] = pack2(v2, v3);   // (r+8, k)|(r+8, k+1)
                }
            }
        }

        // MMA2: Y += S @ V over this warp's 64-key strip (4 k16-steps).
        // NATURAL A order: sf[0]=a0, sf[1]=a1, sf[2]=a2, sf[3]=a3.
        #pragma unroll
        for (int kk = 0; kk < 4; kk++) {
            uint32_t bm[4][4];
            #pragma unroll
            for (int pr = 0; pr < 4; pr++)
                ldsm4(bm[pr], Vst[p] + (pr*16 + lrow) * 256 + (((wn*8 + kk*2 + lhi) ^ (lrow & 7)) << 4));
            #pragma unroll
            for (int mi = 0; mi < 2; mi++)
                #pragma unroll
                for (int ni = 0; ni < 8; ni++)
                    mma16(accY[mi][ni], sf[mi][kk][0], sf[mi][kk][1], sf[mi][kk][2], sf[mi][kk][3],
                          bm[ni>>1][ni & 1], bm[ni>>1][2 + (ni & 1)]);
        }
    }

    // Cross-warp pairwise reduce (wn=1 -> smem, wn=0 adds + stores to gmem).
    __syncthreads();
    float* red = (float*)smem;                   // 128 rows x pitch 65 fp32 = 33.3KB
    if (wn == 1) {
        #pragma unroll
        for (int mi = 0; mi < 2; mi++)
            #pragma unroll
            for (int half = 0; half < 2; half++) {
                const int r = wm*32 + mi*16 + half*8 + (lane >> 2);
                #pragma unroll
                for (int ni = 0; ni < 8; ni++) {
                    red[r * 65 + ni*8 + 2*(lane & 3)    ] = accY[mi][ni][half*2+0];
                    red[r * 65 + ni*8 + 2*(lane & 3) + 1] = accY[mi][ni][half*2+1];
                }
            }
    }
    __syncthreads();
    if (wn == 0) {
        #pragma unroll
        for (int mi = 0; mi < 2; mi++)
            #pragma unroll
            for (int half = 0; half < 2; half++) {
                const int r = wm*32 + mi*16 + half*8 + (lane >> 2);
                const int t = q0 + r;
                float* orow = out + ((size_t)bb * T_ + t) * C_ + h * D_;
                #pragma unroll
                for (int ni = 0; ni < 8; ni++) {
                    const int d = ni*8 + 2*(lane & 3);
                    float v0 = accY[mi][ni][half*2+0] + red[r * 65 + d];
                    float v1 = accY[mi][ni][half*2+1] + red[r * 65 + d + 1];
                    *(float2*)(orow + d) = make_float2(v0, v1);
                }
            }
    }
}

extern "C" void kernel_launch(void* const* d_in, const int* in_sizes, int n_in,
                              void* d_out, int out_size)
{
    const float* x    = (const float*)d_in[0];
    const float* W    = (const float*)d_in[1];
    const float* bias = (const float*)d_in[2];
    float* out = (float*)d_out;

    const int qkv_smem  = 98304;   // 3 x 32KB stages (covers 36.9KB transpose scratch)
    const int attn_smem = 81920;   // Q16K + 2 x (K16K + V16K)
    cudaFuncSetAttribute(qkv_mma_kernel,  cudaFuncAttributeMaxDynamicSharedMemorySize, qkv_smem);
    cudaFuncSetAttribute(attn_mma_kernel, cudaFuncAttributeMaxDynamicSharedMemorySize, attn_smem);

    round_kernel<<<(NX8_ + NW8_ + 255) / 256, 256>>>(x, W);

    dim3 g1(24, 32);
    qkv_mma_kernel<<<g1, 256, qkv_smem>>>(bias);

    dim3 g2(16, 16, 2);
    attn_mma_kernel<<<g2, 256, attn_smem>>>(out);
}

// round 9
// speedup vs baseline: 8.1882x; 1.0455x over previous
#include <cuda_runtime.h>
#include <cuda_fp16.h>
#include <cstdint>

#define B_ 2
#define T_ 2048
#define C_ 1024
#define H_ 16
#define D_ 64
#define M_ (B_*T_)
#define N3_ (3*C_)

// Scratch (fp16 values): Q,K in [b,h,t,d]; V transposed in [b,h,d,t].
__device__ __half g_q [B_*H_*T_*D_];
__device__ __half g_k [B_*H_*T_*D_];
__device__ __half g_vt[B_*H_*D_*T_];
// fp16 copies of x and W
__device__ __half g_x [M_*C_];
__device__ __half g_w [N3_*C_];

// ---------------------------------------------------------------------------
// helpers (base sm_80 PTX)
// ---------------------------------------------------------------------------
__device__ __forceinline__ uint32_t smem_u32(const void* p){
    uint32_t a;
    asm("{ .reg .u64 t; cvta.to.shared.u64 t, %1; cvt.u32.u64 %0, t; }" : "=r"(a) : "l"(p));
    return a;
}
__device__ __forceinline__ uint32_t pack2(float x, float y){
    __half2 h = __floats2half2_rn(x, y);
    return *(uint32_t*)&h;
}
__device__ __forceinline__ void ldsm4(uint32_t (&r)[4], uint32_t a){
    asm volatile("ldmatrix.sync.aligned.m8n8.x4.shared.b16 {%0,%1,%2,%3}, [%4];"
        : "=r"(r[0]), "=r"(r[1]), "=r"(r[2]), "=r"(r[3]) : "r"(a));
}
__device__ __forceinline__ void mma16(float (&d)[4], uint32_t a0, uint32_t a1, uint32_t a2, uint32_t a3,
                                      uint32_t b0, uint32_t b1){
    asm volatile("mma.sync.aligned.m16n8k16.row.col.f32.f16.f16.f32 "
        "{%0,%1,%2,%3}, {%4,%5,%6,%7}, {%8,%9}, {%0,%1,%2,%3};"
        : "+f"(d[0]), "+f"(d[1]), "+f"(d[2]), "+f"(d[3])
        : "r"(a0), "r"(a1), "r"(a2), "r"(a3), "r"(b0), "r"(b1));
}
__device__ __forceinline__ void cp16(uint32_t dst, const void* src){
    asm volatile("cp.async.ca.shared.global [%0], [%1], 16;" :: "r"(dst), "l"(src) : "memory");
}
__device__ __forceinline__ void cp_commit(){ asm volatile("cp.async.commit_group;" ::: "memory"); }
__device__ __forceinline__ void cp_wait0(){ asm volatile("cp.async.wait_group 0;" ::: "memory"); }
__device__ __forceinline__ void cp_wait1(){ asm volatile("cp.async.wait_group 1;" ::: "memory"); }

// ---------------------------------------------------------------------------
// Kernel 0: fp16-convert x and W into g_x, g_w (8 floats -> 8 halves / thread).
// ---------------------------------------------------------------------------
#define NX8_ (M_*C_/8)
#define NW8_ (N3_*C_/8)
__global__ __launch_bounds__(256) void round_kernel(
    const float* __restrict__ x, const float* __restrict__ W)
{
    const int i = blockIdx.x * 256 + threadIdx.x;
    const float4* src; __half* dst;
    if (i < NX8_)              { src = (const float4*)x + (size_t)i * 2;          dst = g_x + (size_t)i * 8; }
    else if (i < NX8_ + NW8_)  { const int j = i - NX8_;
                                 src = (const float4*)W + (size_t)j * 2;          dst = g_w + (size_t)j * 8; }
    else return;
    float4 v0 = __ldg(src), v1 = __ldg(src + 1);
    uint4 o;
    o.x = pack2(v0.x, v0.y); o.y = pack2(v0.z, v0.w);
    o.z = pack2(v1.x, v1.y); o.w = pack2(v1.z, v1.w);
    *(uint4*)dst = o;
}

// ---------------------------------------------------------------------------
// Kernel 1: QKV = g_x @ g_w^T + b  (M=4096, N=3072, K=1024), fp16 m16n8k16.
// 128x128 CTA tile, BK=64 halves (128B rows), 3-stage cp.async, 2 CTAs/SM.
// ---------------------------------------------------------------------------
__global__ void __launch_bounds__(256, 2) qkv_mma_kernel(const float* __restrict__ bias)
{
    extern __shared__ __align__(1024) char smem[];
    const uint32_t s0 = smem_u32(smem);            // 3 stages x (A16K + B16K)
    const int tid = threadIdx.x, lane = tid & 31, wid = tid >> 5;
    const int wm = wid >> 2, wn = wid & 3;
    const int m0 = blockIdx.y * 128, n0 = blockIdx.x * 128;

    const int lrow = (lane & 7) + ((lane >> 3) & 1) * 8;   // ldmatrix row-within-16
    const int lhi  = lane >> 4;                            // ldmatrix chunk-hi

    auto loadAB = [&](int kt, int st) {
        const uint32_t Ab = s0 + st * 32768, Bb = Ab + 16384;
        #pragma unroll
        for (int i = 0; i < 4; i++) {
            const int s = tid + 256 * i, row = s >> 3, c = s & 7;
            const uint32_t off = row * 128 + ((c ^ (row & 7)) << 4);
            cp16(Ab + off, g_x + (size_t)(m0 + row) * C_ + kt * 64 + c * 8);
            cp16(Bb + off, g_w + (size_t)(n0 + row) * C_ + kt * 64 + c * 8);
        }
    };

    float acc[4][4][4] = {};

    loadAB(0, 0); cp_commit();
    loadAB(1, 1); cp_commit();

    for (int kt = 0; kt < 16; kt++) {
        if (kt < 15) cp_wait1(); else cp_wait0();
        __syncthreads();
        if (kt + 2 < 16) { loadAB(kt + 2, (kt + 2) % 3); cp_commit(); }

        const uint32_t Ab = s0 + (kt % 3) * 32768, Bb = Ab + 16384;
        #pragma unroll
        for (int kk = 0; kk < 4; kk++) {
            uint32_t a[4][4], bm[2][4];
            #pragma unroll
            for (int mi = 0; mi < 4; mi++)
                ldsm4(a[mi], Ab + (wm*64 + mi*16 + lrow) * 128 + (((kk*2 + lhi) ^ (lrow & 7)) << 4));
            #pragma unroll
            for (int pr = 0; pr < 2; pr++)
                ldsm4(bm[pr], Bb + (wn*32 + pr*16 + lrow) * 128 + (((kk*2 + lhi) ^ (lrow & 7)) << 4));
            #pragma unroll
            for (int mi = 0; mi < 4; mi++)
                #pragma unroll
                for (int ni = 0; ni < 4; ni++)
                    mma16(acc[mi][ni], a[mi][0], a[mi][1], a[mi][2], a[mi][3],
                          bm[ni>>1][ni & 1], bm[ni>>1][2 + (ni & 1)]);
        }
        __syncthreads();
    }

    const int part = n0 >> 10;   // whole CTA tile lies in one of q/k/v
    if (part < 2) {
        #pragma unroll
        for (int mi = 0; mi < 4; mi++) {
            #pragma unroll
            for (int half = 0; half < 2; half++) {
                const int m = m0 + wm*64 + mi*16 + (lane >> 2) + half*8;
                const int bb = m >> 11, t = m & 2047;
                #pragma unroll
                for (int ni = 0; ni < 4; ni++) {
                    const int n = n0 + wn*32 + ni*8 + 2*(lane & 3);
                    const int hh = (n >> 6) & 15, d = n & 63;
                    const uint32_t hv = pack2(acc[mi][ni][half*2+0] + __ldg(bias + n),
                                              acc[mi][ni][half*2+1] + __ldg(bias + n + 1));
                    __half* dst = (part == 0 ? g_q : g_k) + (((size_t)(bb*H_ + hh) * T_ + t) * D_ + d);
                    *(uint32_t*)dst = hv;
                }
            }
        }
    } else {
        // V: smem transpose (half, pitch 144) -> coalesced [b,h,d,t].
        __half* sv = (__half*)smem;
        #pragma unroll
        for (int mi = 0; mi < 4; mi++) {
            #pragma unroll
            for (int half = 0; half < 2; half++) {
                const int ml = wm*64 + mi*16 + (lane >> 2) + half*8;
                #pragma unroll
                for (int ni = 0; ni < 4; ni++) {
                    const int nl = wn*32 + ni*8 + 2*(lane & 3);
                    const int n = n0 + nl;
                    sv[(nl    ) * 144 + ml] = __float2half_rn(acc[mi][ni][half*2+0] + __ldg(bias + n));
                    sv[(nl + 1) * 144 + ml] = __float2half_rn(acc[mi][ni][half*2+1] + __ldg(bias + n + 1));
                }
            }
        }
        __syncthreads();
        const int hh = (n0 & 1023) >> 6;
        const int bb = m0 >> 11, t0 = m0 & 2047;
        #pragma unroll
        for (int i = 0; i < 8; i++) {
            const int idx = tid + 256 * i;
            const int row = idx >> 4, ch = idx & 15;     // 128 rows x 16 chunks of 8 halves
            uint4 v = *(const uint4*)(sv + row * 144 + ch * 8);
            const int h = hh + (row >> 6), d = row & 63;
            *(uint4*)(g_vt + ((size_t)(bb*H_ + h) * D_ + d) * T_ + t0 + ch * 8) = v;
        }
    }
}

// ---------------------------------------------------------------------------
// Kernel 2: Y = relu(Q K^T * scale, causal) @ V — fp16, S in registers.
// NEW layout: 8 warps x 16 query rows; each warp covers ALL 128 keys (in two
// sequential 64-key halves) and all 64 d-cols. accY=32 regs, accS live=32,
// no cross-warp reduce -> ~115 regs -> 2 CTAs/SM.
// ---------------------------------------------------------------------------
__global__ void __launch_bounds__(256, 2) attn_mma_kernel(float* __restrict__ out)
{
    extern __shared__ __align__(1024) char smem[];
    const uint32_t s0 = smem_u32(smem);
    const uint32_t Qs = s0;                                // 16KB
    const uint32_t Kst[2] = { s0 + 16384, s0 + 49152 };    // 16KB each
    const uint32_t Vst[2] = { s0 + 32768, s0 + 65536 };    // 16KB each; total 80KB

    const int tid = threadIdx.x, lane = tid & 31, wid = tid >> 5;
    const int qt = (int)(gridDim.x - 1) - (int)blockIdx.x; // LPT order
    const int h = blockIdx.y, bb = blockIdx.z;
    const int q0 = qt * 128;
    const size_t bh = (size_t)(bb * H_ + h);
    const __half* Qg  = g_q  + bh * T_ * D_;
    const __half* Kg  = g_k  + bh * T_ * D_;
    const __half* Vtg = g_vt + bh * (size_t)D_ * T_;

    const int lrow = (lane & 7) + ((lane >> 3) & 1) * 8;
    const int lhi  = lane >> 4;

    auto loadKV = [&](int jt, int st) {
        const int j0 = jt * 128;
        #pragma unroll
        for (int i = 0; i < 4; i++) {            // K: 128 keys x 64 d (128B rows)
            int s = tid + 256 * i, row = s >> 3, c = s & 7;
            cp16(Kst[st] + row * 128 + ((c ^ (row & 7)) << 4),
                 Kg + (size_t)(j0 + row) * D_ + c * 8);
        }
        #pragma unroll
        for (int i = 0; i < 4; i++) {            // Vt: 64 d x 128 keys (256B rows)
            int s = tid + 256 * i, row = s >> 4, c = s & 15;
            cp16(Vst[st] + row * 256 + ((c ^ (row & 7)) << 4),
                 Vtg + (size_t)row * T_ + j0 + c * 8);
        }
    };

    // Prologue: Q + KV(0).
    #pragma unroll
    for (int i = 0; i < 4; i++) {
        int s = tid + 256 * i, row = s >> 3, c = s & 7;
        cp16(Qs + row * 128 + ((c ^ (row & 7)) << 4),
             Qg + (size_t)(q0 + row) * D_ + c * 8);
    }
    loadKV(0, 0);
    cp_commit();

    float accY[8][4] = {};
    const int r0 = q0 + wid*16 + (lane >> 2);    // this thread's first query row

    for (int jt = 0; jt <= qt; jt++) {
        const int p = jt & 1;
        const int j0 = jt * 128;
        cp_wait0();
        __syncthreads();
        if (jt < qt) { loadKV(jt + 1, 1 - p); cp_commit(); }

        #pragma unroll
        for (int hf = 0; hf < 2; hf++) {         // two 64-key halves
            // MMA1: S(16 rows x 64 keys) = Q @ K^T  (K=64 -> 4 k16-steps)
            float accS[8][4] = {};
            #pragma unroll
            for (int kk = 0; kk < 4; kk++) {
                uint32_t a[4], bm[4][4];
                ldsm4(a, Qs + (wid*16 + lrow) * 128 + (((kk*2 + lhi) ^ (lrow & 7)) << 4));
                #pragma unroll
                for (int pr = 0; pr < 4; pr++)
                    ldsm4(bm[pr], Kst[p] + (hf*64 + pr*16 + lrow) * 128 + (((kk*2 + lhi) ^ (lrow & 7)) << 4));
                #pragma unroll
                for (int ni = 0; ni < 8; ni++)
                    mma16(accS[ni], a[0], a[1], a[2], a[3],
                          bm[ni>>1][ni & 1], bm[ni>>1][2 + (ni & 1)]);
            }

            // scale + ReLU (+ causal on diagonal tile) -> fp16 A-frags (natural order).
            uint32_t sf[4][4];
            #pragma unroll
            for (int kk = 0; kk < 4; kk++) {
                #pragma unroll
                for (int half = 0; half < 2; half++) {
                    const int ni = kk*2 + half;
                    float v0 = accS[ni][0] * 0.125f;
                    float v1 = accS[ni][1] * 0.125f;
                    float v2 = accS[ni][2] * 0.125f;
                    float v3 = accS[ni][3] * 0.125f;
                    if (jt == qt) {
                        const int k0 = j0 + hf*64 + ni*8 + 2*(lane & 3);
                        v0 = (k0     <= r0    ) ? v0 : 0.f;
                        v1 = (k0 + 1 <= r0    ) ? v1 : 0.f;
                        v2 = (k0     <= r0 + 8) ? v2 : 0.f;
                        v3 = (k0 + 1 <= r0 + 8) ? v3 : 0.f;
                    }
                    v0 = v0 > 0.f ? v0 : 0.f;  v1 = v1 > 0.f ? v1 : 0.f;
                    v2 = v2 > 0.f ? v2 : 0.f;  v3 = v3 > 0.f ? v3 : 0.f;
                    sf[kk][half*2 + 0] = pack2(v0, v1);   // (r, k)|(r, k+1)
                    sf[kk][half*2 + 1] = pack2(v2, v3);   // (r+8, k)|(r+8, k+1)
                }
            }

            // MMA2: Y += S @ V over this 64-key half (4 k16-steps, 64 d-cols).
            #pragma unroll
            for (int kk = 0; kk < 4; kk++) {
                uint32_t bm[4][4];
                #pragma unroll
                for (int pr = 0; pr < 4; pr++)
                    ldsm4(bm[pr], Vst[p] + (pr*16 + lrow) * 256 + (((hf*8 + kk*2 + lhi) ^ (lrow & 7)) << 4));
                #pragma unroll
                for (int ni = 0; ni < 8; ni++)
                    mma16(accY[ni], sf[kk][0], sf[kk][1], sf[kk][2], sf[kk][3],
                          bm[ni>>1][ni & 1], bm[ni>>1][2 + (ni & 1)]);
            }
        }
    }

    // Epilogue: direct store, no reduction. accY[ni][e]: row r0 (+8 for e>=2),
    // col d = ni*8 + 2*(lane&3) + (e&1).
    #pragma unroll
    for (int half = 0; half < 2; half++) {
        const int t = r0 - q0 + half*8 + q0;
        float* orow = out + ((size_t)bb * T_ + t) * C_ + h * D_;
        #pragma unroll
        for (int ni = 0; ni < 8; ni++) {
            const int d = ni*8 + 2*(lane & 3);
            *(float2*)(orow + d) = make_float2(accY[ni][half*2+0], accY[ni][half*2+1]);
        }
    }
}

extern "C" void kernel_launch(void* const* d_in, const int* in_sizes, int n_in,
                              void* d_out, int out_size)
{
    const float* x    = (const float*)d_in[0];
    const float* W    = (const float*)d_in[1];
    const float* bias = (const float*)d_in[2];
    float* out = (float*)d_out;

    const int qkv_smem  = 98304;   // 3 x 32KB stages (covers 36.9KB transpose scratch)
    const int attn_smem = 81920;   // Q16K + 2 x (K16K + V16K); 2 CTAs/SM fit
    cudaFuncSetAttribute(qkv_mma_kernel,  cudaFuncAttributeMaxDynamicSharedMemorySize, qkv_smem);
    cudaFuncSetAttribute(attn_mma_kernel, cudaFuncAttributeMaxDynamicSharedMemorySize, attn_smem);

    round_kernel<<<(NX8_ + NW8_ + 255) / 256, 256>>>(x, W);

    dim3 g1(24, 32);
    qkv_mma_kernel<<<g1, 256, qkv_smem>>>(bias);

    dim3 g2(16, 16, 2);
    attn_mma_kernel<<<g2, 256, attn_smem>>>(out);
}